// round 2
// baseline (speedup 1.0000x reference)
#include <cuda_runtime.h>
#include <math.h>

// Problem constants
#define SQ 2048
#define NH 16
#define DM 1024
#define DH 64

// Scratch (allocation-free: __device__ globals). Layout [head][seq][dhead].
__device__ float g_q[NH * SQ * DH];
__device__ float g_k[NH * SQ * DH];
__device__ float g_v[NH * SQ * DH];
__device__ float g_z[NH * SQ * DH];

// XOR swizzle for transposed smem tiles: keeps float4 quads intact,
// spreads column accesses across banks.
__device__ __forceinline__ int swz(int r, int c) {
    return c ^ (((r >> 2) & 15) << 2);
}

// ---------------------------------------------------------------------------
// Kernel A: per-head projection (2048x1024 @ 1024x64) + bias + RoPE
// grid (32 s-tiles, 16 heads, 3 {q,k,v}), 256 threads
// ---------------------------------------------------------------------------
__global__ __launch_bounds__(256, 1) void proj_rope_kernel(
    const float* __restrict__ xq, const float* __restrict__ xk, const float* __restrict__ xv,
    const float* __restrict__ WQ, const float* __restrict__ bQ,
    const float* __restrict__ WK, const float* __restrict__ bK,
    const float* __restrict__ WV, const float* __restrict__ bV)
{
    __shared__ float At[32][64];   // k-major, swizzled: At[k][s]
    __shared__ float Bs[32][64];   // natural:  Bs[k][e]
    __shared__ float Cs[64][65];   // result staging for rotary

    const int sblk  = blockIdx.x;
    const int h     = blockIdx.y;
    const int which = blockIdx.z;

    const float* X; const float* W; const float* bias; float* out;
    if (which == 0)      { X = xq; W = WQ; bias = bQ; out = g_q; }
    else if (which == 1) { X = xk; W = WK; bias = bK; out = g_k; }
    else                 { X = xv; W = WV; bias = bV; out = g_v; }

    const int tid = threadIdx.x;
    const int tx = tid & 15, ty = tid >> 4;
    const int s0 = sblk * 64;

    float acc[4][4] = {};

    for (int k0 = 0; k0 < DM; k0 += 32) {
        __syncthreads();
        // Load X tile 64(s) x 32(k), store transposed+swizzled
        #pragma unroll
        for (int i = 0; i < 2; i++) {
            int idx = tid + i * 256;
            int r  = idx >> 3;          // s row 0..63
            int c4 = (idx & 7) * 4;     // k col
            const float4 v = *(const float4*)&X[((size_t)(s0 + r) * NH + h) * DM + k0 + c4];
            At[c4 + 0][swz(c4 + 0, r)] = v.x;
            At[c4 + 1][swz(c4 + 1, r)] = v.y;
            At[c4 + 2][swz(c4 + 2, r)] = v.z;
            At[c4 + 3][swz(c4 + 3, r)] = v.w;
        }
        // Load W tile 32(k) x 64(e)
        #pragma unroll
        for (int i = 0; i < 2; i++) {
            int idx = tid + i * 256;
            int r  = idx >> 4;          // k row 0..31
            int c4 = (idx & 15) * 4;    // e col
            *(float4*)&Bs[r][c4] =
                *(const float4*)&W[((size_t)h * DM + k0 + r) * DH + c4];
        }
        __syncthreads();

        #pragma unroll 8
        for (int kk = 0; kk < 32; kk++) {
            float4 a4 = *(const float4*)&At[kk][swz(kk, ty * 4)];
            float4 b4 = *(const float4*)&Bs[kk][tx * 4];
            float a[4] = {a4.x, a4.y, a4.z, a4.w};
            float b[4] = {b4.x, b4.y, b4.z, b4.w};
            #pragma unroll
            for (int ri = 0; ri < 4; ri++)
                #pragma unroll
                for (int ci = 0; ci < 4; ci++)
                    acc[ri][ci] = fmaf(a[ri], b[ci], acc[ri][ci]);
        }
    }
    __syncthreads();

    // Stage result + bias into Cs so rotary can read paired (e +- 32) elements
    #pragma unroll
    for (int ri = 0; ri < 4; ri++)
        #pragma unroll
        for (int ci = 0; ci < 4; ci++)
            Cs[ty * 4 + ri][tx * 4 + ci] = acc[ri][ci] + bias[h * DH + tx * 4 + ci];
    __syncthreads();

    // log2(10000)/32
    const float LOG2_BASE_OVER_HALF = 0.41524101186092029f;

    #pragma unroll
    for (int ri = 0; ri < 4; ri++) {
        int r = ty * 4 + ri;
        int pos = s0 + r;
        #pragma unroll
        for (int ci = 0; ci < 4; ci++) {
            int e = tx * 4 + ci;
            float val;
            if (which < 2) {
                int j = e & 31;
                float inv_freq = exp2f(-(float)j * LOG2_BASE_OVER_HALF);
                float ang = (float)pos * inv_freq;
                float sn, cs;
                sincosf(ang, &sn, &cs);
                float x    = Cs[r][e];
                float flip = (e < 32) ? -Cs[r][e + 32] : Cs[r][e - 32];
                val = x * cs + flip * sn;
            } else {
                val = Cs[r][e];
            }
            out[((size_t)h * SQ + pos) * DH + e] = val;
        }
    }
}

// ---------------------------------------------------------------------------
// Kernel B: causal flash attention. grid (16 paired q-tiles, 16 heads).
// Each block processes q-tile blockIdx.x and q-tile (31 - blockIdx.x):
// total key-tile iterations per block = (x+1) + (32-x) = 33 (perfectly balanced).
// ---------------------------------------------------------------------------
__global__ __launch_bounds__(256, 1) void attn_kernel()
{
    __shared__ float QT[64][64];   // d-major, swizzled: QT[d][q]
    __shared__ float KT[64][64];   // d-major, swizzled: KT[d][k]; reused as PT[k][q]
    __shared__ float Vs[64][64];   // natural: Vs[k][e]

    const int h   = blockIdx.y;
    const int tid = threadIdx.x;
    const int tx = tid & 15, ty = tid >> 4;

    for (int rep = 0; rep < 2; rep++) {
        const int qb = rep ? (31 - (int)blockIdx.x) : (int)blockIdx.x;
        const int q0 = qb * 64;

        __syncthreads();  // protect smem reuse from previous rep
        // Load Q tile transposed+swizzled
        #pragma unroll
        for (int i = 0; i < 4; i++) {
            int idx = tid + i * 256;
            int r  = idx >> 4;           // q row 0..63
            int c4 = (idx & 15) * 4;     // d col
            float4 v = *(const float4*)&g_q[((size_t)h * SQ + q0 + r) * DH + c4];
            QT[c4 + 0][swz(c4 + 0, r)] = v.x;
            QT[c4 + 1][swz(c4 + 1, r)] = v.y;
            QT[c4 + 2][swz(c4 + 2, r)] = v.z;
            QT[c4 + 3][swz(c4 + 3, r)] = v.w;
        }

        float m[4], l[4], o[4][4] = {};
        #pragma unroll
        for (int ri = 0; ri < 4; ri++) { m[ri] = -1e30f; l[ri] = 0.f; }

        for (int kb = 0; kb <= qb; kb++) {
            __syncthreads();  // previous PV done reading KT/Vs (and QT visible on 1st iter)
            // Load K transposed+swizzled, V natural
            #pragma unroll
            for (int i = 0; i < 4; i++) {
                int idx = tid + i * 256;
                int r  = idx >> 4;
                int c4 = (idx & 15) * 4;
                size_t base = ((size_t)h * SQ + kb * 64 + r) * DH + c4;
                float4 kv = *(const float4*)&g_k[base];
                KT[c4 + 0][swz(c4 + 0, r)] = kv.x;
                KT[c4 + 1][swz(c4 + 1, r)] = kv.y;
                KT[c4 + 2][swz(c4 + 2, r)] = kv.z;
                KT[c4 + 3][swz(c4 + 3, r)] = kv.w;
                *(float4*)&Vs[r][c4] = *(const float4*)&g_v[base];
            }
            __syncthreads();

            // S = Q K^T fragment (4 q-rows x 4 k-cols per thread)
            float sf[4][4] = {};
            #pragma unroll 8
            for (int d = 0; d < 64; d++) {
                float4 a4 = *(const float4*)&QT[d][swz(d, ty * 4)];
                float4 b4 = *(const float4*)&KT[d][swz(d, tx * 4)];
                float a[4] = {a4.x, a4.y, a4.z, a4.w};
                float b[4] = {b4.x, b4.y, b4.z, b4.w};
                #pragma unroll
                for (int ri = 0; ri < 4; ri++)
                    #pragma unroll
                    for (int ci = 0; ci < 4; ci++)
                        sf[ri][ci] = fmaf(a[ri], b[ci], sf[ri][ci]);
            }

            // scale + causal mask
            const bool diag = (kb == qb);
            #pragma unroll
            for (int ri = 0; ri < 4; ri++) {
                int qg = q0 + ty * 4 + ri;
                #pragma unroll
                for (int ci = 0; ci < 4; ci++) {
                    int kg = kb * 64 + tx * 4 + ci;
                    float s = sf[ri][ci] * 0.125f;
                    if (diag && kg > qg) s = -1e30f;
                    sf[ri][ci] = s;
                }
            }

            // Online softmax. Row r lives on the 16 lanes sharing ty (xor 1,2,4,8).
            #pragma unroll
            for (int ri = 0; ri < 4; ri++) {
                float rmax = fmaxf(fmaxf(sf[ri][0], sf[ri][1]),
                                   fmaxf(sf[ri][2], sf[ri][3]));
                #pragma unroll
                for (int off = 8; off > 0; off >>= 1)
                    rmax = fmaxf(rmax, __shfl_xor_sync(0xffffffffu, rmax, off));
                float mnew = fmaxf(m[ri], rmax);
                float corr = __expf(m[ri] - mnew);
                float rsum = 0.f;
                #pragma unroll
                for (int ci = 0; ci < 4; ci++) {
                    float p = __expf(sf[ri][ci] - mnew);
                    sf[ri][ci] = p;
                    rsum += p;
                }
                #pragma unroll
                for (int off = 8; off > 0; off >>= 1)
                    rsum += __shfl_xor_sync(0xffffffffu, rsum, off);
                l[ri] = l[ri] * corr + rsum;
                m[ri] = mnew;
                #pragma unroll
                for (int ci = 0; ci < 4; ci++) o[ri][ci] *= corr;
            }

            __syncthreads();  // all threads done reading KT
            // Write P transposed into KT buffer: PT[k][q]
            #pragma unroll
            for (int ri = 0; ri < 4; ri++)
                #pragma unroll
                for (int ci = 0; ci < 4; ci++) {
                    int kc = tx * 4 + ci, qr = ty * 4 + ri;
                    KT[kc][swz(kc, qr)] = sf[ri][ci];
                }
            __syncthreads();

            // O += P V
            #pragma unroll 8
            for (int kj = 0; kj < 64; kj++) {
                float4 p4 = *(const float4*)&KT[kj][swz(kj, ty * 4)];
                float4 v4 = *(const float4*)&Vs[kj][tx * 4];
                float p[4] = {p4.x, p4.y, p4.z, p4.w};
                float v[4] = {v4.x, v4.y, v4.z, v4.w};
                #pragma unroll
                for (int ri = 0; ri < 4; ri++)
                    #pragma unroll
                    for (int ci = 0; ci < 4; ci++)
                        o[ri][ci] = fmaf(p[ri], v[ci], o[ri][ci]);
            }
        }

        // Normalize and write Z
        #pragma unroll
        for (int ri = 0; ri < 4; ri++) {
            float inv = 1.f / l[ri];
            int qg = q0 + ty * 4 + ri;
            #pragma unroll
            for (int ci = 0; ci < 4; ci++)
                g_z[((size_t)h * SQ + qg) * DH + tx * 4 + ci] = o[ri][ci] * inv;
        }
    }
}

// ---------------------------------------------------------------------------
// Kernel C: per-head output projection (2048x64 @ 64x1024) + b_O/16
// grid (32 s-tiles, 16 d-tiles, 16 heads), 256 threads
// ---------------------------------------------------------------------------
__global__ __launch_bounds__(256, 1) void outproj_kernel(
    const float* __restrict__ WO, const float* __restrict__ bO,
    float* __restrict__ out)
{
    __shared__ float Zt[64][64];   // e-major, swizzled: Zt[e][s]
    __shared__ float Ws[64][64];   // natural:  Ws[e][d]

    const int sblk = blockIdx.x;
    const int dblk = blockIdx.y;
    const int h    = blockIdx.z;
    const int tid = threadIdx.x;
    const int tx = tid & 15, ty = tid >> 4;
    const int s0 = sblk * 64, d0 = dblk * 64;

    #pragma unroll
    for (int i = 0; i < 4; i++) {
        int idx = tid + i * 256;
        int r  = idx >> 4;          // row 0..63
        int c4 = (idx & 15) * 4;
        float4 z = *(const float4*)&g_z[((size_t)h * SQ + s0 + r) * DH + c4];
        Zt[c4 + 0][swz(c4 + 0, r)] = z.x;
        Zt[c4 + 1][swz(c4 + 1, r)] = z.y;
        Zt[c4 + 2][swz(c4 + 2, r)] = z.z;
        Zt[c4 + 3][swz(c4 + 3, r)] = z.w;
        *(float4*)&Ws[r][c4] =
            *(const float4*)&WO[((size_t)h * DH + r) * DM + d0 + c4];
    }
    __syncthreads();

    float acc[4][4] = {};
    #pragma unroll 8
    for (int e = 0; e < 64; e++) {
        float4 a4 = *(const float4*)&Zt[e][swz(e, ty * 4)];
        float4 b4 = *(const float4*)&Ws[e][tx * 4];
        float a[4] = {a4.x, a4.y, a4.z, a4.w};
        float b[4] = {b4.x, b4.y, b4.z, b4.w};
        #pragma unroll
        for (int ri = 0; ri < 4; ri++)
            #pragma unroll
            for (int ci = 0; ci < 4; ci++)
                acc[ri][ci] = fmaf(a[ri], b[ci], acc[ri][ci]);
    }

    #pragma unroll
    for (int ri = 0; ri < 4; ri++) {
        int sg = s0 + ty * 4 + ri;
        #pragma unroll
        for (int ci = 0; ci < 4; ci++) {
            int dg = d0 + tx * 4 + ci;
            out[((size_t)sg * NH + h) * DM + dg] = acc[ri][ci] + bO[dg] * (1.0f / 16.0f);
        }
    }
}

// ---------------------------------------------------------------------------
extern "C" void kernel_launch(void* const* d_in, const int* in_sizes, int n_in,
                              void* d_out, int out_size)
{
    (void)in_sizes; (void)n_in; (void)out_size;
    const float* xq = (const float*)d_in[0];
    const float* xk = (const float*)d_in[1];
    const float* xv = (const float*)d_in[2];
    const float* WQ = (const float*)d_in[3];
    const float* bQ = (const float*)d_in[4];
    const float* WK = (const float*)d_in[5];
    const float* bK = (const float*)d_in[6];
    const float* WV = (const float*)d_in[7];
    const float* bV = (const float*)d_in[8];
    const float* WO = (const float*)d_in[9];
    const float* bO = (const float*)d_in[10];
    float* out = (float*)d_out;

    proj_rope_kernel<<<dim3(32, 16, 3), 256>>>(xq, xk, xv, WQ, bQ, WK, bK, WV, bV);
    attn_kernel<<<dim3(16, 16), 256>>>();
    outproj_kernel<<<dim3(32, 16, 16), 256>>>(WO, bO, out);
}

// round 4
// speedup vs baseline: 1.4555x; 1.4555x over previous
#include <cuda_runtime.h>
#include <cstdint>
#include <math.h>

#define SQ 2048
#define NH 16
#define DM 1024
#define DH 64

__device__ float g_q[NH * SQ * DH];
__device__ float g_k[NH * SQ * DH];
__device__ float g_v[NH * SQ * DH];
__device__ float g_z[NH * SQ * DH];
__device__ float g_wt[3][NH * DH * DM];   // W_{Q,K,V}^T: [h][e][k]  (n-major for mma B)
__device__ float g_wot[NH * DM * DH];     // W_O^T:       [h][d][e]  (n-major for mma B)

__device__ __forceinline__ uint32_t smem_u32(const void* p) {
    uint32_t a;
    asm("{ .reg .u64 t; cvta.to.shared.u64 t, %1; cvt.u32.u64 %0, t; }" : "=r"(a) : "l"(p));
    return a;
}
#define SWZ128(x) ((x) ^ (((x) >> 3) & 0x70))

__device__ __forceinline__ float to_tf32(float x) {
    float y;
    asm("cvt.rna.tf32.f32 %0, %1;" : "=f"(y) : "f"(x));
    return y;
}
__device__ __forceinline__ void ldsm_x4(uint32_t& r0, uint32_t& r1, uint32_t& r2,
                                        uint32_t& r3, uint32_t addr) {
    asm volatile("ldmatrix.sync.aligned.m8n8.x4.shared.b16 {%0,%1,%2,%3}, [%4];"
                 : "=r"(r0), "=r"(r1), "=r"(r2), "=r"(r3) : "r"(addr));
}
__device__ __forceinline__ void mma_tf32(float* c, const uint32_t* a,
                                         uint32_t b0, uint32_t b1) {
    asm volatile(
        "mma.sync.aligned.m16n8k8.row.col.f32.tf32.tf32.f32 "
        "{%0,%1,%2,%3}, {%4,%5,%6,%7}, {%8,%9}, {%0,%1,%2,%3};"
        : "+f"(c[0]), "+f"(c[1]), "+f"(c[2]), "+f"(c[3])
        : "r"(a[0]), "r"(a[1]), "r"(a[2]), "r"(a[3]), "r"(b0), "r"(b1));
}

// ---------------- W transpose -------------------------------------------------
__global__ void transpose_w_kernel(const float* __restrict__ WQ, const float* __restrict__ WK,
                                   const float* __restrict__ WV, const float* __restrict__ WO)
{
    __shared__ float t[32][33];
    const int m = blockIdx.y >> 4, h = blockIdx.y & 15;
    const float* src; float* dst; int R, C;
    if (m == 0)      { src = WQ + (size_t)h*DM*DH; dst = g_wt[0] + (size_t)h*DH*DM; R = DM; C = DH; }
    else if (m == 1) { src = WK + (size_t)h*DM*DH; dst = g_wt[1] + (size_t)h*DH*DM; R = DM; C = DH; }
    else if (m == 2) { src = WV + (size_t)h*DM*DH; dst = g_wt[2] + (size_t)h*DH*DM; R = DM; C = DH; }
    else             { src = WO + (size_t)h*DH*DM; dst = g_wot   + (size_t)h*DM*DH; R = DH; C = DM; }
    const int nrt = R / 32, rt = blockIdx.x % nrt, ct = blockIdx.x / nrt;
    const int x = ct * 32 + threadIdx.x;
    #pragma unroll
    for (int j = 0; j < 4; j++)
        t[threadIdx.y + j*8][threadIdx.x] = src[(size_t)(rt*32 + threadIdx.y + j*8) * C + x];
    __syncthreads();
    const int xo = rt * 32 + threadIdx.x;
    #pragma unroll
    for (int j = 0; j < 4; j++)
        dst[(size_t)(ct*32 + threadIdx.y + j*8) * R + xo] = t[threadIdx.x][threadIdx.y + j*8];
}

// ---------------- Projection via HMMA tf32 + bias + RoPE ----------------------
// grid (16 s-tiles, 16 heads, 3), 256 threads. D[128s x 64e] = X @ W, K=1024.
// Warp tile: 16(M) x 64(N); each thread holds both RoPE partners (e, e+32).
__global__ __launch_bounds__(256, 1) void proj_mma_kernel(
    const float* __restrict__ xq, const float* __restrict__ xk, const float* __restrict__ xv,
    const float* __restrict__ bQ, const float* __restrict__ bK, const float* __restrict__ bV)
{
    __shared__ float As[128 * 32];   // 16KB, 128B rows, SWZ128
    __shared__ float Bs[64 * 32];    //  8KB, 128B rows, SWZ128

    const int tid = threadIdx.x, w = tid >> 5, lane = tid & 31;
    const int h = blockIdx.y, which = blockIdx.z;
    const int s0 = blockIdx.x * 128;

    const float* X    = (which == 0) ? xq : (which == 1) ? xk : xv;
    const float* bias = (which == 0) ? bQ : (which == 1) ? bK : bV;
    const float* WT   = g_wt[which] + (size_t)h * DH * DM;
    float* out        = (which == 0) ? g_q : (which == 1) ? g_k : g_v;

    const uint32_t sbA = smem_u32(As), sbB = smem_u32(Bs);
    const int mw = w * 16;
    const int g  = lane >> 3, l7 = lane & 7;

    float acc[8][4] = {};   // 8 n8-tiles x {c0,c1,c2,c3}

    for (int c = 0; c < 32; c++) {
        const int k0 = c * 32;
        __syncthreads();
        #pragma unroll
        for (int i = 0; i < 4; i++) {            // A: 128 x 32 -> 1024 quads
            int idx = tid + i * 256, r = idx >> 3, q = idx & 7;
            float4 v = *(const float4*)&X[(((size_t)(s0 + r)) * NH + h) * DM + k0 + q*4];
            v.x = to_tf32(v.x); v.y = to_tf32(v.y); v.z = to_tf32(v.z); v.w = to_tf32(v.w);
            *(float4*)((uint8_t*)As + SWZ128((uint32_t)(r*128 + q*16))) = v;
        }
        #pragma unroll
        for (int i = 0; i < 2; i++) {            // B: 64 x 32 -> 512 quads
            int idx = tid + i * 256, n = idx >> 3, q = idx & 7;
            float4 v = *(const float4*)&WT[(size_t)n * DM + k0 + q*4];
            v.x = to_tf32(v.x); v.y = to_tf32(v.y); v.z = to_tf32(v.z); v.w = to_tf32(v.w);
            *(float4*)((uint8_t*)Bs + SWZ128((uint32_t)(n*128 + q*16))) = v;
        }
        __syncthreads();

        #pragma unroll
        for (int kk = 0; kk < 4; kk++) {
            const int kb = kk * 32;
            uint32_t a[4];
            {   // A fragment (m16 x k8) via ldmatrix.x4
                int row = mw + ((g & 1) << 3) + l7;
                int byo = kb + ((g >> 1) << 4);
                ldsm_x4(a[0], a[1], a[2], a[3], sbA + SWZ128((uint32_t)(row*128 + byo)));
            }
            uint32_t b[16];
            #pragma unroll
            for (int nb = 0; nb < 4; nb++) {    // B fragments for n-tiles 2nb, 2nb+1
                int row = nb * 16 + ((g >> 1) << 3) + l7;
                int byo = kb + ((g & 1) << 4);
                ldsm_x4(b[nb*4+0], b[nb*4+1], b[nb*4+2], b[nb*4+3],
                        sbB + SWZ128((uint32_t)(row*128 + byo)));
            }
            #pragma unroll
            for (int ni = 0; ni < 8; ni++)
                mma_tf32(acc[ni], a, b[(ni >> 1)*4 + (ni & 1)*2],
                                     b[(ni >> 1)*4 + (ni & 1)*2 + 1]);
        }
    }

    // Epilogue: bias + RoPE (register-local) + store.
    const int r0 = mw + (lane >> 2);     // local row (c0,c1); r0+8 -> (c2,c3)
    const int ec = (lane & 3) * 2;       // col offset within n8 tile

    #pragma unroll
    for (int ni = 0; ni < 8; ni++) {
        float bv0 = bias[h * DH + ni*8 + ec];
        float bv1 = bias[h * DH + ni*8 + ec + 1];
        acc[ni][0] += bv0; acc[ni][1] += bv1;
        acc[ni][2] += bv0; acc[ni][3] += bv1;
    }

    if (which < 2) {
        const float L2B = 0.41524101186092029f;   // log2(10000)/32
        #pragma unroll
        for (int ni = 0; ni < 4; ni++) {
            #pragma unroll
            for (int cc = 0; cc < 2; cc++) {
                int j = ni*8 + ec + cc;
                float invf = exp2f(-(float)j * L2B);
                #pragma unroll
                for (int rr = 0; rr < 2; rr++) {
                    float pos = (float)(s0 + r0 + rr*8);
                    float ang = pos * invf;
                    float sn, cs; sincosf(ang, &sn, &cs);
                    int ci = rr*2 + cc;
                    float x = acc[ni][ci], y = acc[ni+4][ci];
                    acc[ni][ci]   = x*cs - y*sn;
                    acc[ni+4][ci] = y*cs + x*sn;
                }
            }
        }
    }

    #pragma unroll
    for (int ni = 0; ni < 8; ni++) {
        int e = ni*8 + ec;
        *(float2*)&out[((size_t)h*SQ + s0 + r0    ) * DH + e] = make_float2(acc[ni][0], acc[ni][1]);
        *(float2*)&out[((size_t)h*SQ + s0 + r0 + 8) * DH + e] = make_float2(acc[ni][2], acc[ni][3]);
    }
}

// ---------------- Attention (SIMT, balanced pairing; proven) ------------------
__device__ __forceinline__ int swz(int r, int c) { return c ^ (((r >> 2) & 15) << 2); }

__global__ __launch_bounds__(256, 1) void attn_kernel()
{
    __shared__ float QT[64][64];
    __shared__ float KT[64][64];
    __shared__ float Vs[64][64];
    const int h = blockIdx.y, tid = threadIdx.x;
    const int tx = tid & 15, ty = tid >> 4;

    for (int rep = 0; rep < 2; rep++) {
        const int qb = rep ? (31 - (int)blockIdx.x) : (int)blockIdx.x;
        const int q0 = qb * 64;
        __syncthreads();
        #pragma unroll
        for (int i = 0; i < 4; i++) {
            int idx = tid + i * 256, r = idx >> 4, c4 = (idx & 15) * 4;
            float4 v = *(const float4*)&g_q[((size_t)h * SQ + q0 + r) * DH + c4];
            QT[c4+0][swz(c4+0, r)] = v.x; QT[c4+1][swz(c4+1, r)] = v.y;
            QT[c4+2][swz(c4+2, r)] = v.z; QT[c4+3][swz(c4+3, r)] = v.w;
        }
        float m[4], l[4], o[4][4] = {};
        #pragma unroll
        for (int ri = 0; ri < 4; ri++) { m[ri] = -1e30f; l[ri] = 0.f; }

        for (int kb = 0; kb <= qb; kb++) {
            __syncthreads();
            #pragma unroll
            for (int i = 0; i < 4; i++) {
                int idx = tid + i * 256, r = idx >> 4, c4 = (idx & 15) * 4;
                size_t base = ((size_t)h * SQ + kb * 64 + r) * DH + c4;
                float4 kv = *(const float4*)&g_k[base];
                KT[c4+0][swz(c4+0, r)] = kv.x; KT[c4+1][swz(c4+1, r)] = kv.y;
                KT[c4+2][swz(c4+2, r)] = kv.z; KT[c4+3][swz(c4+3, r)] = kv.w;
                *(float4*)&Vs[r][c4] = *(const float4*)&g_v[base];
            }
            __syncthreads();

            float sf[4][4] = {};
            #pragma unroll 8
            for (int d = 0; d < 64; d++) {
                float4 a4 = *(const float4*)&QT[d][swz(d, ty*4)];
                float4 b4 = *(const float4*)&KT[d][swz(d, tx*4)];
                float a[4] = {a4.x,a4.y,a4.z,a4.w}, b[4] = {b4.x,b4.y,b4.z,b4.w};
                #pragma unroll
                for (int ri = 0; ri < 4; ri++)
                    #pragma unroll
                    for (int ci = 0; ci < 4; ci++)
                        sf[ri][ci] = fmaf(a[ri], b[ci], sf[ri][ci]);
            }
            const bool diag = (kb == qb);
            #pragma unroll
            for (int ri = 0; ri < 4; ri++) {
                int qg = q0 + ty*4 + ri;
                #pragma unroll
                for (int ci = 0; ci < 4; ci++) {
                    int kg = kb*64 + tx*4 + ci;
                    float s = sf[ri][ci] * 0.125f;
                    if (diag && kg > qg) s = -1e30f;
                    sf[ri][ci] = s;
                }
            }
            #pragma unroll
            for (int ri = 0; ri < 4; ri++) {
                float rmax = fmaxf(fmaxf(sf[ri][0], sf[ri][1]), fmaxf(sf[ri][2], sf[ri][3]));
                #pragma unroll
                for (int off = 8; off > 0; off >>= 1)
                    rmax = fmaxf(rmax, __shfl_xor_sync(0xffffffffu, rmax, off));
                float mnew = fmaxf(m[ri], rmax);
                float corr = __expf(m[ri] - mnew);
                float rsum = 0.f;
                #pragma unroll
                for (int ci = 0; ci < 4; ci++) {
                    float p = __expf(sf[ri][ci] - mnew);
                    sf[ri][ci] = p; rsum += p;
                }
                #pragma unroll
                for (int off = 8; off > 0; off >>= 1)
                    rsum += __shfl_xor_sync(0xffffffffu, rsum, off);
                l[ri] = l[ri] * corr + rsum; m[ri] = mnew;
                #pragma unroll
                for (int ci = 0; ci < 4; ci++) o[ri][ci] *= corr;
            }
            __syncthreads();
            #pragma unroll
            for (int ri = 0; ri < 4; ri++)
                #pragma unroll
                for (int ci = 0; ci < 4; ci++) {
                    int kc = tx*4 + ci, qr = ty*4 + ri;
                    KT[kc][swz(kc, qr)] = sf[ri][ci];
                }
            __syncthreads();
            #pragma unroll 8
            for (int kj = 0; kj < 64; kj++) {
                float4 p4 = *(const float4*)&KT[kj][swz(kj, ty*4)];
                float4 v4 = *(const float4*)&Vs[kj][tx*4];
                float p[4] = {p4.x,p4.y,p4.z,p4.w}, v[4] = {v4.x,v4.y,v4.z,v4.w};
                #pragma unroll
                for (int ri = 0; ri < 4; ri++)
                    #pragma unroll
                    for (int ci = 0; ci < 4; ci++)
                        o[ri][ci] = fmaf(p[ri], v[ci], o[ri][ci]);
            }
        }
        #pragma unroll
        for (int ri = 0; ri < 4; ri++) {
            float inv = 1.f / l[ri];
            int qg = q0 + ty*4 + ri;
            #pragma unroll
            for (int ci = 0; ci < 4; ci++)
                g_z[((size_t)h * SQ + qg) * DH + tx*4 + ci] = o[ri][ci] * inv;
        }
    }
}

// ---------------- Output projection via HMMA tf32 -----------------------------
// grid (16 s, 16 d, 16 h), 256 threads. D[128s x 64d] = Z[128x64] @ WO^T slice.
__global__ __launch_bounds__(256, 1) void outproj_mma_kernel(
    const float* __restrict__ bO, float* __restrict__ out)
{
    __shared__ float As[128 * 32];
    __shared__ float Bs[64 * 32];

    const int tid = threadIdx.x, w = tid >> 5, lane = tid & 31;
    const int s0 = blockIdx.x * 128, d0 = blockIdx.y * 64, h = blockIdx.z;
    const float* WOT = g_wot + (size_t)h * DM * DH;

    const uint32_t sbA = smem_u32(As), sbB = smem_u32(Bs);
    const int mw = w * 16;
    const int g  = lane >> 3, l7 = lane & 7;

    float acc[8][4] = {};

    #pragma unroll
    for (int c = 0; c < 2; c++) {
        const int k0 = c * 32;
        __syncthreads();
        #pragma unroll
        for (int i = 0; i < 4; i++) {
            int idx = tid + i * 256, r = idx >> 3, q = idx & 7;
            float4 v = *(const float4*)&g_z[((size_t)h*SQ + s0 + r) * DH + k0 + q*4];
            v.x = to_tf32(v.x); v.y = to_tf32(v.y); v.z = to_tf32(v.z); v.w = to_tf32(v.w);
            *(float4*)((uint8_t*)As + SWZ128((uint32_t)(r*128 + q*16))) = v;
        }
        #pragma unroll
        for (int i = 0; i < 2; i++) {
            int idx = tid + i * 256, n = idx >> 3, q = idx & 7;
            float4 v = *(const float4*)&WOT[(size_t)(d0 + n) * DH + k0 + q*4];
            v.x = to_tf32(v.x); v.y = to_tf32(v.y); v.z = to_tf32(v.z); v.w = to_tf32(v.w);
            *(float4*)((uint8_t*)Bs + SWZ128((uint32_t)(n*128 + q*16))) = v;
        }
        __syncthreads();

        #pragma unroll
        for (int kk = 0; kk < 4; kk++) {
            const int kb = kk * 32;
            uint32_t a[4];
            {
                int row = mw + ((g & 1) << 3) + l7;
                int byo = kb + ((g >> 1) << 4);
                ldsm_x4(a[0], a[1], a[2], a[3], sbA + SWZ128((uint32_t)(row*128 + byo)));
            }
            uint32_t b[16];
            #pragma unroll
            for (int nb = 0; nb < 4; nb++) {
                int row = nb * 16 + ((g >> 1) << 3) + l7;
                int byo = kb + ((g & 1) << 4);
                ldsm_x4(b[nb*4+0], b[nb*4+1], b[nb*4+2], b[nb*4+3],
                        sbB + SWZ128((uint32_t)(row*128 + byo)));
            }
            #pragma unroll
            for (int ni = 0; ni < 8; ni++)
                mma_tf32(acc[ni], a, b[(ni >> 1)*4 + (ni & 1)*2],
                                     b[(ni >> 1)*4 + (ni & 1)*2 + 1]);
        }
    }

    const int r0 = mw + (lane >> 2);
    const int ec = (lane & 3) * 2;
    #pragma unroll
    for (int ni = 0; ni < 8; ni++) {
        int dg = d0 + ni*8 + ec;
        float b0 = bO[dg] * 0.0625f, b1 = bO[dg + 1] * 0.0625f;
        int sg0 = s0 + r0, sg1 = sg0 + 8;
        *(float2*)&out[((size_t)sg0 * NH + h) * DM + dg] = make_float2(acc[ni][0] + b0, acc[ni][1] + b1);
        *(float2*)&out[((size_t)sg1 * NH + h) * DM + dg] = make_float2(acc[ni][2] + b0, acc[ni][3] + b1);
    }
}

// -------------------------------------------------------------------------------
extern "C" void kernel_launch(void* const* d_in, const int* in_sizes, int n_in,
                              void* d_out, int out_size)
{
    (void)in_sizes; (void)n_in; (void)out_size;
    const float* xq = (const float*)d_in[0];
    const float* xk = (const float*)d_in[1];
    const float* xv = (const float*)d_in[2];
    const float* WQ = (const float*)d_in[3];
    const float* bQ = (const float*)d_in[4];
    const float* WK = (const float*)d_in[5];
    const float* bK = (const float*)d_in[6];
    const float* WV = (const float*)d_in[7];
    const float* bV = (const float*)d_in[8];
    const float* WO = (const float*)d_in[9];
    const float* bO = (const float*)d_in[10];
    float* out = (float*)d_out;

    transpose_w_kernel<<<dim3(64, 64), dim3(32, 8)>>>(WQ, WK, WV, WO);
    proj_mma_kernel<<<dim3(16, 16, 3), 256>>>(xq, xk, xv, bQ, bK, bV);
    attn_kernel<<<dim3(16, 16), 256>>>();
    outproj_mma_kernel<<<dim3(16, 16, 16), 256>>>(bO, out);
}

// round 5
// speedup vs baseline: 2.1896x; 1.5044x over previous
#include <cuda_runtime.h>
#include <cstdint>
#include <math.h>

#define SQ 2048
#define NH 16
#define DM 1024
#define DH 64

__device__ float g_q[NH * SQ * DH];
__device__ float g_k[NH * SQ * DH];
__device__ float g_v[NH * SQ * DH];
__device__ float g_z[NH * SQ * DH];
__device__ float g_wt[3][NH * DH * DM];   // W_{Q,K,V}^T: [h][e][k]
__device__ float g_wot[NH * DM * DH];     // W_O^T:       [h][d][e]

__device__ __forceinline__ uint32_t smem_u32(const void* p) {
    uint32_t a;
    asm("{ .reg .u64 t; cvta.to.shared.u64 t, %1; cvt.u32.u64 %0, t; }" : "=r"(a) : "l"(p));
    return a;
}
#define SWZ128(x) ((x) ^ (((x) >> 3) & 0x70))

__device__ __forceinline__ float to_tf32(float x) {
    float y;
    asm("cvt.rna.tf32.f32 %0, %1;" : "=f"(y) : "f"(x));
    return y;
}
__device__ __forceinline__ void ldsm_x4(uint32_t& r0, uint32_t& r1, uint32_t& r2,
                                        uint32_t& r3, uint32_t addr) {
    asm volatile("ldmatrix.sync.aligned.m8n8.x4.shared.b16 {%0,%1,%2,%3}, [%4];"
                 : "=r"(r0), "=r"(r1), "=r"(r2), "=r"(r3) : "r"(addr));
}
__device__ __forceinline__ void mma_tf32(float* c, const uint32_t* a,
                                         uint32_t b0, uint32_t b1) {
    asm volatile(
        "mma.sync.aligned.m16n8k8.row.col.f32.tf32.tf32.f32 "
        "{%0,%1,%2,%3}, {%4,%5,%6,%7}, {%8,%9}, {%0,%1,%2,%3};"
        : "+f"(c[0]), "+f"(c[1]), "+f"(c[2]), "+f"(c[3])
        : "r"(a[0]), "r"(a[1]), "r"(a[2]), "r"(a[3]), "r"(b0), "r"(b1));
}

// ---------------- W transpose -------------------------------------------------
__global__ void transpose_w_kernel(const float* __restrict__ WQ, const float* __restrict__ WK,
                                   const float* __restrict__ WV, const float* __restrict__ WO)
{
    __shared__ float t[32][33];
    const int m = blockIdx.y >> 4, h = blockIdx.y & 15;
    const float* src; float* dst; int R, C;
    if (m == 0)      { src = WQ + (size_t)h*DM*DH; dst = g_wt[0] + (size_t)h*DH*DM; R = DM; C = DH; }
    else if (m == 1) { src = WK + (size_t)h*DM*DH; dst = g_wt[1] + (size_t)h*DH*DM; R = DM; C = DH; }
    else if (m == 2) { src = WV + (size_t)h*DM*DH; dst = g_wt[2] + (size_t)h*DH*DM; R = DM; C = DH; }
    else             { src = WO + (size_t)h*DH*DM; dst = g_wot   + (size_t)h*DM*DH; R = DH; C = DM; }
    const int nrt = R / 32, rt = blockIdx.x % nrt, ct = blockIdx.x / nrt;
    const int x = ct * 32 + threadIdx.x;
    #pragma unroll
    for (int j = 0; j < 4; j++)
        t[threadIdx.y + j*8][threadIdx.x] = src[(size_t)(rt*32 + threadIdx.y + j*8) * C + x];
    __syncthreads();
    const int xo = rt * 32 + threadIdx.x;
    #pragma unroll
    for (int j = 0; j < 4; j++)
        dst[(size_t)(ct*32 + threadIdx.y + j*8) * R + xo] = t[threadIdx.x][threadIdx.y + j*8];
}

// ---------------- Projection via HMMA tf32 + bias + RoPE ----------------------
__global__ __launch_bounds__(256, 1) void proj_mma_kernel(
    const float* __restrict__ xq, const float* __restrict__ xk, const float* __restrict__ xv,
    const float* __restrict__ bQ, const float* __restrict__ bK, const float* __restrict__ bV)
{
    __shared__ float As[128 * 32];
    __shared__ float Bs[64 * 32];

    const int tid = threadIdx.x, w = tid >> 5, lane = tid & 31;
    const int h = blockIdx.y, which = blockIdx.z;
    const int s0 = blockIdx.x * 128;

    const float* X    = (which == 0) ? xq : (which == 1) ? xk : xv;
    const float* bias = (which == 0) ? bQ : (which == 1) ? bK : bV;
    const float* WT   = g_wt[which] + (size_t)h * DH * DM;
    float* out        = (which == 0) ? g_q : (which == 1) ? g_k : g_v;

    const uint32_t sbA = smem_u32(As), sbB = smem_u32(Bs);
    const int mw = w * 16;
    const int g  = lane >> 3, l7 = lane & 7;

    float acc[8][4] = {};

    for (int c = 0; c < 32; c++) {
        const int k0 = c * 32;
        __syncthreads();
        #pragma unroll
        for (int i = 0; i < 4; i++) {
            int idx = tid + i * 256, r = idx >> 3, q = idx & 7;
            float4 v = *(const float4*)&X[(((size_t)(s0 + r)) * NH + h) * DM + k0 + q*4];
            v.x = to_tf32(v.x); v.y = to_tf32(v.y); v.z = to_tf32(v.z); v.w = to_tf32(v.w);
            *(float4*)((uint8_t*)As + SWZ128((uint32_t)(r*128 + q*16))) = v;
        }
        #pragma unroll
        for (int i = 0; i < 2; i++) {
            int idx = tid + i * 256, n = idx >> 3, q = idx & 7;
            float4 v = *(const float4*)&WT[(size_t)n * DM + k0 + q*4];
            v.x = to_tf32(v.x); v.y = to_tf32(v.y); v.z = to_tf32(v.z); v.w = to_tf32(v.w);
            *(float4*)((uint8_t*)Bs + SWZ128((uint32_t)(n*128 + q*16))) = v;
        }
        __syncthreads();

        #pragma unroll
        for (int kk = 0; kk < 4; kk++) {
            const int kb = kk * 32;
            uint32_t a[4];
            {
                int row = mw + ((g & 1) << 3) + l7;
                int byo = kb + ((g >> 1) << 4);
                ldsm_x4(a[0], a[1], a[2], a[3], sbA + SWZ128((uint32_t)(row*128 + byo)));
            }
            uint32_t b[16];
            #pragma unroll
            for (int nb = 0; nb < 4; nb++) {
                int row = nb * 16 + ((g >> 1) << 3) + l7;
                int byo = kb + ((g & 1) << 4);
                ldsm_x4(b[nb*4+0], b[nb*4+1], b[nb*4+2], b[nb*4+3],
                        sbB + SWZ128((uint32_t)(row*128 + byo)));
            }
            #pragma unroll
            for (int ni = 0; ni < 8; ni++)
                mma_tf32(acc[ni], a, b[(ni >> 1)*4 + (ni & 1)*2],
                                     b[(ni >> 1)*4 + (ni & 1)*2 + 1]);
        }
    }

    const int r0 = mw + (lane >> 2);
    const int ec = (lane & 3) * 2;

    #pragma unroll
    for (int ni = 0; ni < 8; ni++) {
        float bv0 = bias[h * DH + ni*8 + ec];
        float bv1 = bias[h * DH + ni*8 + ec + 1];
        acc[ni][0] += bv0; acc[ni][1] += bv1;
        acc[ni][2] += bv0; acc[ni][3] += bv1;
    }

    if (which < 2) {
        const float L2B = 0.41524101186092029f;
        #pragma unroll
        for (int ni = 0; ni < 4; ni++) {
            #pragma unroll
            for (int cc = 0; cc < 2; cc++) {
                int j = ni*8 + ec + cc;
                float invf = exp2f(-(float)j * L2B);
                #pragma unroll
                for (int rr = 0; rr < 2; rr++) {
                    float pos = (float)(s0 + r0 + rr*8);
                    float sn, cs; sincosf(pos * invf, &sn, &cs);
                    int ci = rr*2 + cc;
                    float x = acc[ni][ci], y = acc[ni+4][ci];
                    acc[ni][ci]   = x*cs - y*sn;
                    acc[ni+4][ci] = y*cs + x*sn;
                }
            }
        }
    }

    #pragma unroll
    for (int ni = 0; ni < 8; ni++) {
        int e = ni*8 + ec;
        *(float2*)&out[((size_t)h*SQ + s0 + r0    ) * DH + e] = make_float2(acc[ni][0], acc[ni][1]);
        *(float2*)&out[((size_t)h*SQ + s0 + r0 + 8) * DH + e] = make_float2(acc[ni][2], acc[ni][3]);
    }
}

// ---------------- Attention via HMMA tf32 (flash, causal, paired) -------------
// grid (16 pairs, 16 heads), 128 threads. Q-tile 64 rows; key tiles of 64.
// Warp w owns q-rows [16w, 16w+16). Qs buffer is reused for P (warp-private rows).
__global__ __launch_bounds__(128, 1) void attn_mma_kernel()
{
    __shared__ float Qs[2][64 * 32];   // Q staging, then P
    __shared__ float Ks[2][64 * 32];
    __shared__ float Vt[2][64 * 32];   // V transposed: [e][k]

    const int tid = threadIdx.x, w = tid >> 5, lane = tid & 31;
    const int h = blockIdx.y;
    const int g = lane >> 3, l7 = lane & 7;
    const int mw = w * 16;
    const int r_loc = lane >> 2, ec = (lane & 3) * 2;
    const uint32_t sQ = smem_u32(Qs), sK = smem_u32(Ks), sV = smem_u32(Vt);

    for (int rep = 0; rep < 2; rep++) {
        const int qb = rep ? (31 - (int)blockIdx.x) : (int)blockIdx.x;
        const int q0 = qb * 64;

        __syncthreads();
        #pragma unroll
        for (int i = 0; i < 8; i++) {      // Q tile 64x64 -> 2 chunks of 64x32
            int idx = tid + i * 128, r = idx >> 4, q = idx & 15;
            float4 v = *(const float4*)&g_q[((size_t)h*SQ + q0 + r) * DH + q*4];
            v.x = to_tf32(v.x); v.y = to_tf32(v.y); v.z = to_tf32(v.z); v.w = to_tf32(v.w);
            *(float4*)((uint8_t*)Qs + (q>>3)*8192 + SWZ128((uint32_t)(r*128 + (q&7)*16))) = v;
        }
        __syncthreads();

        uint32_t qa[8][4];
        #pragma unroll
        for (int ds = 0; ds < 8; ds++) {
            int row = mw + ((g & 1) << 3) + l7;
            int byo = (ds & 3) * 32 + ((g >> 1) << 4);
            ldsm_x4(qa[ds][0], qa[ds][1], qa[ds][2], qa[ds][3],
                    sQ + (ds >> 2)*8192 + SWZ128((uint32_t)(row*128 + byo)));
        }

        float m0 = -1e30f, m1 = -1e30f, l0 = 0.f, l1 = 0.f;
        float oa[8][4] = {};

        for (int kt = 0; kt <= qb; kt++) {
            __syncthreads();               // prior iter done reading Ks/Vt
            #pragma unroll
            for (int i = 0; i < 8; i++) {  // K + V^T tiles
                int idx = tid + i * 128, r = idx >> 4, q = idx & 15;
                size_t base = ((size_t)h*SQ + kt*64 + r) * DH + q*4;
                float4 kv = *(const float4*)&g_k[base];
                kv.x = to_tf32(kv.x); kv.y = to_tf32(kv.y);
                kv.z = to_tf32(kv.z); kv.w = to_tf32(kv.w);
                *(float4*)((uint8_t*)Ks + (q>>3)*8192 + SWZ128((uint32_t)(r*128 + (q&7)*16))) = kv;
                float4 vv = *(const float4*)&g_v[base];
                const float vf[4] = {vv.x, vv.y, vv.z, vv.w};
                #pragma unroll
                for (int j = 0; j < 4; j++) {
                    int e = q*4 + j;
                    *(float*)((uint8_t*)Vt + (r>>5)*8192 +
                              SWZ128((uint32_t)(e*128 + (r & 31)*4))) = to_tf32(vf[j]);
                }
            }
            __syncthreads();

            // S = Q K^T (m16 x n64 per warp)
            float sacc[8][4] = {};
            #pragma unroll
            for (int ds = 0; ds < 8; ds++) {
                uint32_t b[16];
                #pragma unroll
                for (int nb = 0; nb < 4; nb++) {
                    int row = nb*16 + ((g >> 1) << 3) + l7;
                    int byo = (ds & 3)*32 + ((g & 1) << 4);
                    ldsm_x4(b[nb*4+0], b[nb*4+1], b[nb*4+2], b[nb*4+3],
                            sK + (ds >> 2)*8192 + SWZ128((uint32_t)(row*128 + byo)));
                }
                #pragma unroll
                for (int ni = 0; ni < 8; ni++)
                    mma_tf32(sacc[ni], qa[ds], b[(ni>>1)*4 + (ni&1)*2],
                                               b[(ni>>1)*4 + (ni&1)*2 + 1]);
            }

            // scale + causal mask (only diagonal tile needs it)
            const bool diag = (kt == qb);
            #pragma unroll
            for (int ni = 0; ni < 8; ni++) {
                #pragma unroll
                for (int ci = 0; ci < 4; ci++) sacc[ni][ci] *= 0.125f;
                if (diag) {
                    int col = ni*8 + ec;
                    int row0 = mw + r_loc, row1 = row0 + 8;
                    if (col     > row0) sacc[ni][0] = -1e30f;
                    if (col + 1 > row0) sacc[ni][1] = -1e30f;
                    if (col     > row1) sacc[ni][2] = -1e30f;
                    if (col + 1 > row1) sacc[ni][3] = -1e30f;
                }
            }

            // online softmax (rows spread across the 4-lane quad)
            float rx0 = -1e30f, rx1 = -1e30f;
            #pragma unroll
            for (int ni = 0; ni < 8; ni++) {
                rx0 = fmaxf(rx0, fmaxf(sacc[ni][0], sacc[ni][1]));
                rx1 = fmaxf(rx1, fmaxf(sacc[ni][2], sacc[ni][3]));
            }
            rx0 = fmaxf(rx0, __shfl_xor_sync(0xffffffffu, rx0, 1));
            rx0 = fmaxf(rx0, __shfl_xor_sync(0xffffffffu, rx0, 2));
            rx1 = fmaxf(rx1, __shfl_xor_sync(0xffffffffu, rx1, 1));
            rx1 = fmaxf(rx1, __shfl_xor_sync(0xffffffffu, rx1, 2));
            float mn0 = fmaxf(m0, rx0), mn1 = fmaxf(m1, rx1);
            float c0 = __expf(m0 - mn0), c1 = __expf(m1 - mn1);
            float su0 = 0.f, su1 = 0.f;
            #pragma unroll
            for (int ni = 0; ni < 8; ni++) {
                sacc[ni][0] = __expf(sacc[ni][0] - mn0);
                sacc[ni][1] = __expf(sacc[ni][1] - mn0);
                sacc[ni][2] = __expf(sacc[ni][2] - mn1);
                sacc[ni][3] = __expf(sacc[ni][3] - mn1);
                su0 += sacc[ni][0] + sacc[ni][1];
                su1 += sacc[ni][2] + sacc[ni][3];
            }
            su0 += __shfl_xor_sync(0xffffffffu, su0, 1);
            su0 += __shfl_xor_sync(0xffffffffu, su0, 2);
            su1 += __shfl_xor_sync(0xffffffffu, su1, 1);
            su1 += __shfl_xor_sync(0xffffffffu, su1, 2);
            l0 = l0 * c0 + su0; l1 = l1 * c1 + su1;
            m0 = mn0; m1 = mn1;
            #pragma unroll
            for (int ni = 0; ni < 8; ni++) {
                oa[ni][0] *= c0; oa[ni][1] *= c0;
                oa[ni][2] *= c1; oa[ni][3] *= c1;
            }

            // write P into Qs (warp-private rows), then PV mma
            #pragma unroll
            for (int ni = 0; ni < 8; ni++) {
                int col = ni*8 + ec, ch = col >> 5, cc = col & 31;
                int row0 = mw + r_loc;
                float2 p0 = make_float2(to_tf32(sacc[ni][0]), to_tf32(sacc[ni][1]));
                float2 p1 = make_float2(to_tf32(sacc[ni][2]), to_tf32(sacc[ni][3]));
                *(float2*)((uint8_t*)Qs + ch*8192 + SWZ128((uint32_t)(row0*128 + cc*4))) = p0;
                *(float2*)((uint8_t*)Qs + ch*8192 + SWZ128((uint32_t)((row0+8)*128 + cc*4))) = p1;
            }
            __syncwarp();

            #pragma unroll
            for (int ks = 0; ks < 8; ks++) {
                uint32_t a[4];
                int row = mw + ((g & 1) << 3) + l7;
                int byo = (ks & 3)*32 + ((g >> 1) << 4);
                ldsm_x4(a[0], a[1], a[2], a[3],
                        sQ + (ks >> 2)*8192 + SWZ128((uint32_t)(row*128 + byo)));
                uint32_t b[16];
                #pragma unroll
                for (int nb = 0; nb < 4; nb++) {
                    int rowb = nb*16 + ((g >> 1) << 3) + l7;
                    int byob = (ks & 3)*32 + ((g & 1) << 4);
                    ldsm_x4(b[nb*4+0], b[nb*4+1], b[nb*4+2], b[nb*4+3],
                            sV + (ks >> 2)*8192 + SWZ128((uint32_t)(rowb*128 + byob)));
                }
                #pragma unroll
                for (int ni = 0; ni < 8; ni++)
                    mma_tf32(oa[ni], a, b[(ni>>1)*4 + (ni&1)*2],
                                        b[(ni>>1)*4 + (ni&1)*2 + 1]);
            }
        }

        // normalize + store Z
        float inv0 = 1.f / l0, inv1 = 1.f / l1;
        int row0 = q0 + mw + r_loc;
        #pragma unroll
        for (int ni = 0; ni < 8; ni++) {
            int e = ni*8 + ec;
            *(float2*)&g_z[((size_t)h*SQ + row0    ) * DH + e] =
                make_float2(oa[ni][0]*inv0, oa[ni][1]*inv0);
            *(float2*)&g_z[((size_t)h*SQ + row0 + 8) * DH + e] =
                make_float2(oa[ni][2]*inv1, oa[ni][3]*inv1);
        }
    }
}

// ---------------- Output projection via HMMA tf32 (N=128 per block) -----------
// grid (16 s, 8 d, 16 h), 256 threads. D[128s x 128d] = Z[128x64] @ WO^T slice.
__global__ __launch_bounds__(256, 1) void outproj_mma_kernel(
    const float* __restrict__ bO, float* __restrict__ out)
{
    __shared__ float As[128 * 32];
    __shared__ float Bs[128 * 32];

    const int tid = threadIdx.x, w = tid >> 5, lane = tid & 31;
    const int s0 = blockIdx.x * 128, d0 = blockIdx.y * 128, h = blockIdx.z;
    const float* WOT = g_wot + (size_t)h * DM * DH;

    const uint32_t sbA = smem_u32(As), sbB = smem_u32(Bs);
    const int mw = w * 16;
    const int g  = lane >> 3, l7 = lane & 7;

    float acc[16][4] = {};

    #pragma unroll
    for (int c = 0; c < 2; c++) {
        const int k0 = c * 32;
        __syncthreads();
        #pragma unroll
        for (int i = 0; i < 4; i++) {
            int idx = tid + i * 256, r = idx >> 3, q = idx & 7;
            float4 v = *(const float4*)&g_z[((size_t)h*SQ + s0 + r) * DH + k0 + q*4];
            v.x = to_tf32(v.x); v.y = to_tf32(v.y); v.z = to_tf32(v.z); v.w = to_tf32(v.w);
            *(float4*)((uint8_t*)As + SWZ128((uint32_t)(r*128 + q*16))) = v;
        }
        #pragma unroll
        for (int i = 0; i < 4; i++) {
            int idx = tid + i * 256, n = idx >> 3, q = idx & 7;
            float4 v = *(const float4*)&WOT[(size_t)(d0 + n) * DH + k0 + q*4];
            v.x = to_tf32(v.x); v.y = to_tf32(v.y); v.z = to_tf32(v.z); v.w = to_tf32(v.w);
            *(float4*)((uint8_t*)Bs + SWZ128((uint32_t)(n*128 + q*16))) = v;
        }
        __syncthreads();

        #pragma unroll
        for (int kk = 0; kk < 4; kk++) {
            const int kb = kk * 32;
            uint32_t a[4];
            {
                int row = mw + ((g & 1) << 3) + l7;
                int byo = kb + ((g >> 1) << 4);
                ldsm_x4(a[0], a[1], a[2], a[3], sbA + SWZ128((uint32_t)(row*128 + byo)));
            }
            uint32_t b[32];
            #pragma unroll
            for (int nb = 0; nb < 8; nb++) {
                int row = nb * 16 + ((g >> 1) << 3) + l7;
                int byo = kb + ((g & 1) << 4);
                ldsm_x4(b[nb*4+0], b[nb*4+1], b[nb*4+2], b[nb*4+3],
                        sbB + SWZ128((uint32_t)(row*128 + byo)));
            }
            #pragma unroll
            for (int ni = 0; ni < 16; ni++)
                mma_tf32(acc[ni], a, b[(ni >> 1)*4 + (ni & 1)*2],
                                     b[(ni >> 1)*4 + (ni & 1)*2 + 1]);
        }
    }

    const int r0 = mw + (lane >> 2);
    const int ec = (lane & 3) * 2;
    #pragma unroll
    for (int ni = 0; ni < 16; ni++) {
        int dg = d0 + ni*8 + ec;
        float b0 = bO[dg] * 0.0625f, b1 = bO[dg + 1] * 0.0625f;
        int sg0 = s0 + r0, sg1 = sg0 + 8;
        *(float2*)&out[((size_t)sg0 * NH + h) * DM + dg] = make_float2(acc[ni][0] + b0, acc[ni][1] + b1);
        *(float2*)&out[((size_t)sg1 * NH + h) * DM + dg] = make_float2(acc[ni][2] + b0, acc[ni][3] + b1);
    }
}

// -------------------------------------------------------------------------------
extern "C" void kernel_launch(void* const* d_in, const int* in_sizes, int n_in,
                              void* d_out, int out_size)
{
    (void)in_sizes; (void)n_in; (void)out_size;
    const float* xq = (const float*)d_in[0];
    const float* xk = (const float*)d_in[1];
    const float* xv = (const float*)d_in[2];
    const float* WQ = (const float*)d_in[3];
    const float* bQ = (const float*)d_in[4];
    const float* WK = (const float*)d_in[5];
    const float* bK = (const float*)d_in[6];
    const float* WV = (const float*)d_in[7];
    const float* bV = (const float*)d_in[8];
    const float* WO = (const float*)d_in[9];
    const float* bO = (const float*)d_in[10];
    float* out = (float*)d_out;

    transpose_w_kernel<<<dim3(64, 64), dim3(32, 8)>>>(WQ, WK, WV, WO);
    proj_mma_kernel<<<dim3(16, 16, 3), 256>>>(xq, xk, xv, bQ, bK, bV);
    attn_mma_kernel<<<dim3(16, 16), 128>>>();
    outproj_mma_kernel<<<dim3(16, 8, 16), 256>>>(bO, out);
}

// round 6
// speedup vs baseline: 2.2413x; 1.0236x over previous
#include <cuda_runtime.h>
#include <cstdint>
#include <math.h>

#define SQ 2048
#define NH 16
#define DM 1024
#define DH 64

__device__ float g_q[NH * SQ * DH];
__device__ float g_k[NH * SQ * DH];
__device__ float g_v[NH * SQ * DH];
__device__ float g_vt[NH * DH * SQ];      // V^T: [h][e][s], tf32-rounded
__device__ float g_z[NH * SQ * DH];
__device__ float g_wt[3][NH * DH * DM];   // W^T, tf32-rounded
__device__ float g_wot[NH * DM * DH];     // W_O^T, tf32-rounded

__device__ __forceinline__ uint32_t smem_u32(const void* p) {
    uint32_t a;
    asm("{ .reg .u64 t; cvta.to.shared.u64 t, %1; cvt.u32.u64 %0, t; }" : "=r"(a) : "l"(p));
    return a;
}
#define SWZ128(x) ((x) ^ (((x) >> 3) & 0x70))

__device__ __forceinline__ float to_tf32(float x) {
    float y;
    asm("cvt.rna.tf32.f32 %0, %1;" : "=f"(y) : "f"(x));
    return y;
}
__device__ __forceinline__ void ldsm_x4(uint32_t& r0, uint32_t& r1, uint32_t& r2,
                                        uint32_t& r3, uint32_t addr) {
    asm volatile("ldmatrix.sync.aligned.m8n8.x4.shared.b16 {%0,%1,%2,%3}, [%4];"
                 : "=r"(r0), "=r"(r1), "=r"(r2), "=r"(r3) : "r"(addr));
}
__device__ __forceinline__ void mma_tf32(float* c, const uint32_t* a,
                                         uint32_t b0, uint32_t b1) {
    asm volatile(
        "mma.sync.aligned.m16n8k8.row.col.f32.tf32.tf32.f32 "
        "{%0,%1,%2,%3}, {%4,%5,%6,%7}, {%8,%9}, {%0,%1,%2,%3};"
        : "+f"(c[0]), "+f"(c[1]), "+f"(c[2]), "+f"(c[3])
        : "r"(a[0]), "r"(a[1]), "r"(a[2]), "r"(a[3]), "r"(b0), "r"(b1));
}
#define CP_ASYNC16(dst, src) \
    asm volatile("cp.async.cg.shared.global [%0], [%1], 16;" :: "r"(dst), "l"(src))
#define CP_COMMIT() asm volatile("cp.async.commit_group;" ::: "memory")
#define CP_WAIT(n)  asm volatile("cp.async.wait_group %0;" :: "n"(n) : "memory")

// ---------------- W transpose (+tf32 round) -----------------------------------
__global__ void transpose_w_kernel(const float* __restrict__ WQ, const float* __restrict__ WK,
                                   const float* __restrict__ WV, const float* __restrict__ WO)
{
    __shared__ float t[32][33];
    const int m = blockIdx.y >> 4, h = blockIdx.y & 15;
    const float* src; float* dst; int R, C;
    if (m == 0)      { src = WQ + (size_t)h*DM*DH; dst = g_wt[0] + (size_t)h*DH*DM; R = DM; C = DH; }
    else if (m == 1) { src = WK + (size_t)h*DM*DH; dst = g_wt[1] + (size_t)h*DH*DM; R = DM; C = DH; }
    else if (m == 2) { src = WV + (size_t)h*DM*DH; dst = g_wt[2] + (size_t)h*DH*DM; R = DM; C = DH; }
    else             { src = WO + (size_t)h*DH*DM; dst = g_wot   + (size_t)h*DM*DH; R = DH; C = DM; }
    const int nrt = R / 32, rt = blockIdx.x % nrt, ct = blockIdx.x / nrt;
    const int x = ct * 32 + threadIdx.x;
    #pragma unroll
    for (int j = 0; j < 4; j++)
        t[threadIdx.y + j*8][threadIdx.x] =
            to_tf32(src[(size_t)(rt*32 + threadIdx.y + j*8) * C + x]);
    __syncthreads();
    const int xo = rt * 32 + threadIdx.x;
    #pragma unroll
    for (int j = 0; j < 4; j++)
        dst[(size_t)(ct*32 + threadIdx.y + j*8) * R + xo] = t[threadIdx.x][threadIdx.y + j*8];
}

// ---------------- V transpose: g_v [h][s][e] -> g_vt [h][e][s] -----------------
__global__ void vtrans_kernel()
{
    __shared__ float t[32][33];
    const int h = blockIdx.z;
    const int s0 = blockIdx.x * 32, e0 = blockIdx.y * 32;
    #pragma unroll
    for (int j = 0; j < 4; j++)
        t[threadIdx.y + j*8][threadIdx.x] =
            g_v[((size_t)h*SQ + s0 + threadIdx.y + j*8) * DH + e0 + threadIdx.x];
    __syncthreads();
    #pragma unroll
    for (int j = 0; j < 4; j++)
        g_vt[((size_t)h*DH + e0 + threadIdx.y + j*8) * SQ + s0 + threadIdx.x] =
            t[threadIdx.x][threadIdx.y + j*8];
}

// ---------------- Projection via HMMA tf32, register-staged pipeline -----------
__global__ __launch_bounds__(256, 1) void proj_mma_kernel(
    const float* __restrict__ xq, const float* __restrict__ xk, const float* __restrict__ xv,
    const float* __restrict__ bQ, const float* __restrict__ bK, const float* __restrict__ bV)
{
    __shared__ float As[2][128 * 32];  // 32KB
    __shared__ float Bs[2][64 * 32];   // 16KB

    const int tid = threadIdx.x, w = tid >> 5, lane = tid & 31;
    const int h = blockIdx.y, which = blockIdx.z;
    const int s0 = blockIdx.x * 128;

    const float* X    = (which == 0) ? xq : (which == 1) ? xk : xv;
    const float* bias = (which == 0) ? bQ : (which == 1) ? bK : bV;
    const float* WT   = g_wt[which] + (size_t)h * DH * DM;
    float* out        = (which == 0) ? g_q : (which == 1) ? g_k : g_v;

    const int mw = w * 16;
    const int g  = lane >> 3, l7 = lane & 7;
    const int ra = tid >> 3, qa8 = tid & 7;          // A: row 0..31(+32i), quad
    const int rb = (tid & 127) >> 3;                 // B rows via 2 half-blocks

    float acc[8][4] = {};
    float4 ar[4], br[2];

    // prologue: load chunk 0
    #pragma unroll
    for (int i = 0; i < 4; i++)
        ar[i] = *(const float4*)&X[(((size_t)(s0 + ra + i*32)) * NH + h) * DM + qa8*4];
    #pragma unroll
    for (int i = 0; i < 2; i++)
        br[i] = *(const float4*)&WT[(size_t)(rb + (tid>>7)*16 + i*32) * DM + qa8*4];

    #pragma unroll 1
    for (int c = 0; c < 32; c++) {
        const int buf = c & 1;
        // STS current regs (A with cvt; B pre-rounded)
        #pragma unroll
        for (int i = 0; i < 4; i++) {
            float4 v = ar[i];
            v.x = to_tf32(v.x); v.y = to_tf32(v.y); v.z = to_tf32(v.z); v.w = to_tf32(v.w);
            *(float4*)((uint8_t*)As[buf] + SWZ128((uint32_t)((ra + i*32)*128 + qa8*16))) = v;
        }
        #pragma unroll
        for (int i = 0; i < 2; i++)
            *(float4*)((uint8_t*)Bs[buf] +
                SWZ128((uint32_t)((rb + (tid>>7)*16 + i*32)*128 + qa8*16))) = br[i];
        __syncthreads();

        // prefetch next chunk into regs
        if (c < 31) {
            const int k0 = (c + 1) * 32;
            #pragma unroll
            for (int i = 0; i < 4; i++)
                ar[i] = *(const float4*)&X[(((size_t)(s0 + ra + i*32)) * NH + h) * DM + k0 + qa8*4];
            #pragma unroll
            for (int i = 0; i < 2; i++)
                br[i] = *(const float4*)&WT[(size_t)(rb + (tid>>7)*16 + i*32) * DM + k0 + qa8*4];
        }

        const uint32_t sbA = smem_u32(As[buf]), sbB = smem_u32(Bs[buf]);
        #pragma unroll
        for (int kk = 0; kk < 4; kk++) {
            const int kb = kk * 32;
            uint32_t a[4];
            {
                int row = mw + ((g & 1) << 3) + l7;
                int byo = kb + ((g >> 1) << 4);
                ldsm_x4(a[0], a[1], a[2], a[3], sbA + SWZ128((uint32_t)(row*128 + byo)));
            }
            uint32_t b[16];
            #pragma unroll
            for (int nb = 0; nb < 4; nb++) {
                int row = nb * 16 + ((g >> 1) << 3) + l7;
                int byo = kb + ((g & 1) << 4);
                ldsm_x4(b[nb*4+0], b[nb*4+1], b[nb*4+2], b[nb*4+3],
                        sbB + SWZ128((uint32_t)(row*128 + byo)));
            }
            #pragma unroll
            for (int ni = 0; ni < 8; ni++)
                mma_tf32(acc[ni], a, b[(ni >> 1)*4 + (ni & 1)*2],
                                     b[(ni >> 1)*4 + (ni & 1)*2 + 1]);
        }
        __syncthreads();
    }

    const int r0 = mw + (lane >> 2);
    const int ec = (lane & 3) * 2;

    #pragma unroll
    for (int ni = 0; ni < 8; ni++) {
        float bv0 = bias[h * DH + ni*8 + ec];
        float bv1 = bias[h * DH + ni*8 + ec + 1];
        acc[ni][0] += bv0; acc[ni][1] += bv1;
        acc[ni][2] += bv0; acc[ni][3] += bv1;
    }

    if (which < 2) {
        const float L2B = 0.41524101186092029f;
        #pragma unroll
        for (int ni = 0; ni < 4; ni++) {
            #pragma unroll
            for (int cc = 0; cc < 2; cc++) {
                int j = ni*8 + ec + cc;
                float invf = exp2f(-(float)j * L2B);
                #pragma unroll
                for (int rr = 0; rr < 2; rr++) {
                    float pos = (float)(s0 + r0 + rr*8);
                    float sn, cs; sincosf(pos * invf, &sn, &cs);
                    int ci = rr*2 + cc;
                    float x = acc[ni][ci], y = acc[ni+4][ci];
                    acc[ni][ci]   = x*cs - y*sn;
                    acc[ni+4][ci] = y*cs + x*sn;
                }
            }
        }
    }

    #pragma unroll
    for (int ni = 0; ni < 8; ni++) {
        int e = ni*8 + ec;
        *(float2*)&out[((size_t)h*SQ + s0 + r0    ) * DH + e] =
            make_float2(to_tf32(acc[ni][0]), to_tf32(acc[ni][1]));
        *(float2*)&out[((size_t)h*SQ + s0 + r0 + 8) * DH + e] =
            make_float2(to_tf32(acc[ni][2]), to_tf32(acc[ni][3]));
    }
}

// ---------------- Attention via HMMA tf32, cp.async double-buffered ------------
// dynamic smem: Q/P @0 (16KB), K @16384 (2x16KB), V @49152 (2x16KB) = 80KB
__global__ __launch_bounds__(128, 1) void attn_mma_kernel()
{
    extern __shared__ uint8_t dsm[];
    const uint32_t sQ = smem_u32(dsm);
    const uint32_t sK = sQ + 16384;
    const uint32_t sV = sQ + 49152;

    const int tid = threadIdx.x, w = tid >> 5, lane = tid & 31;
    const int h = blockIdx.y;
    const int g = lane >> 3, l7 = lane & 7;
    const int mw = w * 16;
    const int r_loc = lane >> 2, ec = (lane & 3) * 2;

    for (int rep = 0; rep < 2; rep++) {
        const int qb = rep ? (31 - (int)blockIdx.x) : (int)blockIdx.x;
        const int q0 = qb * 64;

        __syncthreads();   // previous rep fully done with smem
        // Q tile via cp.async (group 1)
        #pragma unroll
        for (int i = 0; i < 8; i++) {
            int idx = tid + i * 128, r = idx >> 4, q = idx & 15;
            uint32_t off = (uint32_t)((q>>3)*8192) + SWZ128((uint32_t)(r*128 + (q&7)*16));
            CP_ASYNC16(sQ + off, &g_q[((size_t)h*SQ + q0 + r) * DH + q*4]);
        }
        CP_COMMIT();
        // prefetch K/V tile 0 (group 2)
        #pragma unroll
        for (int i = 0; i < 8; i++) {
            int idx = tid + i * 128, r = idx >> 4, q = idx & 15;
            uint32_t off = (uint32_t)((q>>3)*8192) + SWZ128((uint32_t)(r*128 + (q&7)*16));
            CP_ASYNC16(sK + off, &g_k [((size_t)h*SQ + r) * DH + q*4]);
            CP_ASYNC16(sV + off, &g_vt[((size_t)h*DH + r) * SQ + q*4]);
        }
        CP_COMMIT();
        CP_WAIT(1);        // Q landed
        __syncthreads();

        uint32_t qa[8][4];
        #pragma unroll
        for (int ds = 0; ds < 8; ds++) {
            int row = mw + ((g & 1) << 3) + l7;
            int byo = (ds & 3) * 32 + ((g >> 1) << 4);
            ldsm_x4(qa[ds][0], qa[ds][1], qa[ds][2], qa[ds][3],
                    sQ + (uint32_t)((ds >> 2)*8192) + SWZ128((uint32_t)(row*128 + byo)));
        }

        float m0 = -1e30f, m1 = -1e30f, l0 = 0.f, l1 = 0.f;
        float oa[8][4] = {};

        for (int kt = 0; kt <= qb; kt++) {
            const uint32_t kb_off = (uint32_t)((kt & 1) * 16384);
            CP_WAIT(0);
            __syncthreads();
            if (kt < qb) {
                const int kk0 = (kt + 1) * 64;
                const uint32_t nb_off = (uint32_t)(((kt + 1) & 1) * 16384);
                #pragma unroll
                for (int i = 0; i < 8; i++) {
                    int idx = tid + i * 128, r = idx >> 4, q = idx & 15;
                    uint32_t off = nb_off + (uint32_t)((q>>3)*8192)
                                 + SWZ128((uint32_t)(r*128 + (q&7)*16));
                    CP_ASYNC16(sK + off, &g_k [((size_t)h*SQ + kk0 + r) * DH + q*4]);
                    CP_ASYNC16(sV + off, &g_vt[((size_t)h*DH + r) * SQ + kk0 + q*4]);
                }
                CP_COMMIT();
            }

            // S = Q K^T
            float sacc[8][4] = {};
            #pragma unroll
            for (int ds = 0; ds < 8; ds++) {
                uint32_t b[16];
                #pragma unroll
                for (int nb = 0; nb < 4; nb++) {
                    int row = nb*16 + ((g >> 1) << 3) + l7;
                    int byo = (ds & 3)*32 + ((g & 1) << 4);
                    ldsm_x4(b[nb*4+0], b[nb*4+1], b[nb*4+2], b[nb*4+3],
                            sK + kb_off + (uint32_t)((ds >> 2)*8192)
                               + SWZ128((uint32_t)(row*128 + byo)));
                }
                #pragma unroll
                for (int ni = 0; ni < 8; ni++)
                    mma_tf32(sacc[ni], qa[ds], b[(ni>>1)*4 + (ni&1)*2],
                                               b[(ni>>1)*4 + (ni&1)*2 + 1]);
            }

            const bool diag = (kt == qb);
            #pragma unroll
            for (int ni = 0; ni < 8; ni++) {
                #pragma unroll
                for (int ci = 0; ci < 4; ci++) sacc[ni][ci] *= 0.125f;
                if (diag) {
                    int col = ni*8 + ec;
                    int row0 = mw + r_loc, row1 = row0 + 8;
                    if (col     > row0) sacc[ni][0] = -1e30f;
                    if (col + 1 > row0) sacc[ni][1] = -1e30f;
                    if (col     > row1) sacc[ni][2] = -1e30f;
                    if (col + 1 > row1) sacc[ni][3] = -1e30f;
                }
            }

            float rx0 = -1e30f, rx1 = -1e30f;
            #pragma unroll
            for (int ni = 0; ni < 8; ni++) {
                rx0 = fmaxf(rx0, fmaxf(sacc[ni][0], sacc[ni][1]));
                rx1 = fmaxf(rx1, fmaxf(sacc[ni][2], sacc[ni][3]));
            }
            rx0 = fmaxf(rx0, __shfl_xor_sync(0xffffffffu, rx0, 1));
            rx0 = fmaxf(rx0, __shfl_xor_sync(0xffffffffu, rx0, 2));
            rx1 = fmaxf(rx1, __shfl_xor_sync(0xffffffffu, rx1, 1));
            rx1 = fmaxf(rx1, __shfl_xor_sync(0xffffffffu, rx1, 2));
            float mn0 = fmaxf(m0, rx0), mn1 = fmaxf(m1, rx1);
            float c0 = __expf(m0 - mn0), c1 = __expf(m1 - mn1);
            float su0 = 0.f, su1 = 0.f;
            #pragma unroll
            for (int ni = 0; ni < 8; ni++) {
                sacc[ni][0] = __expf(sacc[ni][0] - mn0);
                sacc[ni][1] = __expf(sacc[ni][1] - mn0);
                sacc[ni][2] = __expf(sacc[ni][2] - mn1);
                sacc[ni][3] = __expf(sacc[ni][3] - mn1);
                su0 += sacc[ni][0] + sacc[ni][1];
                su1 += sacc[ni][2] + sacc[ni][3];
            }
            su0 += __shfl_xor_sync(0xffffffffu, su0, 1);
            su0 += __shfl_xor_sync(0xffffffffu, su0, 2);
            su1 += __shfl_xor_sync(0xffffffffu, su1, 1);
            su1 += __shfl_xor_sync(0xffffffffu, su1, 2);
            l0 = l0 * c0 + su0; l1 = l1 * c1 + su1;
            m0 = mn0; m1 = mn1;
            #pragma unroll
            for (int ni = 0; ni < 8; ni++) {
                oa[ni][0] *= c0; oa[ni][1] *= c0;
                oa[ni][2] *= c1; oa[ni][3] *= c1;
            }

            // P -> sQ (warp-private rows)
            #pragma unroll
            for (int ni = 0; ni < 8; ni++) {
                int col = ni*8 + ec, ch = col >> 5, cc = col & 31;
                int row0 = mw + r_loc;
                float2 p0 = make_float2(to_tf32(sacc[ni][0]), to_tf32(sacc[ni][1]));
                float2 p1 = make_float2(to_tf32(sacc[ni][2]), to_tf32(sacc[ni][3]));
                *(float2*)(dsm + ch*8192 + SWZ128((uint32_t)(row0*128 + cc*4))) = p0;
                *(float2*)(dsm + ch*8192 + SWZ128((uint32_t)((row0+8)*128 + cc*4))) = p1;
            }
            __syncwarp();

            #pragma unroll
            for (int ks = 0; ks < 8; ks++) {
                uint32_t a[4];
                int row = mw + ((g & 1) << 3) + l7;
                int byo = (ks & 3)*32 + ((g >> 1) << 4);
                ldsm_x4(a[0], a[1], a[2], a[3],
                        sQ + (uint32_t)((ks >> 2)*8192) + SWZ128((uint32_t)(row*128 + byo)));
                uint32_t b[16];
                #pragma unroll
                for (int nb = 0; nb < 4; nb++) {
                    int rowb = nb*16 + ((g >> 1) << 3) + l7;
                    int byob = (ks & 3)*32 + ((g & 1) << 4);
                    ldsm_x4(b[nb*4+0], b[nb*4+1], b[nb*4+2], b[nb*4+3],
                            sV + kb_off + (uint32_t)((ks >> 2)*8192)
                               + SWZ128((uint32_t)(rowb*128 + byob)));
                }
                #pragma unroll
                for (int ni = 0; ni < 8; ni++)
                    mma_tf32(oa[ni], a, b[(ni>>1)*4 + (ni&1)*2],
                                        b[(ni>>1)*4 + (ni&1)*2 + 1]);
            }
        }

        float inv0 = 1.f / l0, inv1 = 1.f / l1;
        int row0 = q0 + mw + r_loc;
        #pragma unroll
        for (int ni = 0; ni < 8; ni++) {
            int e = ni*8 + ec;
            *(float2*)&g_z[((size_t)h*SQ + row0    ) * DH + e] =
                make_float2(to_tf32(oa[ni][0]*inv0), to_tf32(oa[ni][1]*inv0));
            *(float2*)&g_z[((size_t)h*SQ + row0 + 8) * DH + e] =
                make_float2(to_tf32(oa[ni][2]*inv1), to_tf32(oa[ni][3]*inv1));
        }
    }
}

// ---------------- Output projection via HMMA tf32 ------------------------------
__global__ __launch_bounds__(256, 1) void outproj_mma_kernel(
    const float* __restrict__ bO, float* __restrict__ out)
{
    __shared__ float As[128 * 32];
    __shared__ float Bs[128 * 32];

    const int tid = threadIdx.x, w = tid >> 5, lane = tid & 31;
    const int s0 = blockIdx.x * 128, d0 = blockIdx.y * 128, h = blockIdx.z;
    const float* WOT = g_wot + (size_t)h * DM * DH;

    const uint32_t sbA = smem_u32(As), sbB = smem_u32(Bs);
    const int mw = w * 16;
    const int g  = lane >> 3, l7 = lane & 7;

    float acc[16][4] = {};

    #pragma unroll
    for (int c = 0; c < 2; c++) {
        const int k0 = c * 32;
        __syncthreads();
        #pragma unroll
        for (int i = 0; i < 4; i++) {
            int idx = tid + i * 256, r = idx >> 3, q = idx & 7;
            *(float4*)((uint8_t*)As + SWZ128((uint32_t)(r*128 + q*16))) =
                *(const float4*)&g_z[((size_t)h*SQ + s0 + r) * DH + k0 + q*4];
        }
        #pragma unroll
        for (int i = 0; i < 4; i++) {
            int idx = tid + i * 256, n = idx >> 3, q = idx & 7;
            *(float4*)((uint8_t*)Bs + SWZ128((uint32_t)(n*128 + q*16))) =
                *(const float4*)&WOT[(size_t)(d0 + n) * DH + k0 + q*4];
        }
        __syncthreads();

        #pragma unroll
        for (int kk = 0; kk < 4; kk++) {
            const int kb = kk * 32;
            uint32_t a[4];
            {
                int row = mw + ((g & 1) << 3) + l7;
                int byo = kb + ((g >> 1) << 4);
                ldsm_x4(a[0], a[1], a[2], a[3], sbA + SWZ128((uint32_t)(row*128 + byo)));
            }
            uint32_t b[32];
            #pragma unroll
            for (int nb = 0; nb < 8; nb++) {
                int row = nb * 16 + ((g >> 1) << 3) + l7;
                int byo = kb + ((g & 1) << 4);
                ldsm_x4(b[nb*4+0], b[nb*4+1], b[nb*4+2], b[nb*4+3],
                        sbB + SWZ128((uint32_t)(row*128 + byo)));
            }
            #pragma unroll
            for (int ni = 0; ni < 16; ni++)
                mma_tf32(acc[ni], a, b[(ni >> 1)*4 + (ni & 1)*2],
                                     b[(ni >> 1)*4 + (ni & 1)*2 + 1]);
        }
    }

    const int r0 = mw + (lane >> 2);
    const int ec = (lane & 3) * 2;
    #pragma unroll
    for (int ni = 0; ni < 16; ni++) {
        int dg = d0 + ni*8 + ec;
        float b0 = bO[dg] * 0.0625f, b1 = bO[dg + 1] * 0.0625f;
        int sg0 = s0 + r0, sg1 = sg0 + 8;
        *(float2*)&out[((size_t)sg0 * NH + h) * DM + dg] = make_float2(acc[ni][0] + b0, acc[ni][1] + b1);
        *(float2*)&out[((size_t)sg1 * NH + h) * DM + dg] = make_float2(acc[ni][2] + b0, acc[ni][3] + b1);
    }
}

// -------------------------------------------------------------------------------
extern "C" void kernel_launch(void* const* d_in, const int* in_sizes, int n_in,
                              void* d_out, int out_size)
{
    (void)in_sizes; (void)n_in; (void)out_size;
    const float* xq = (const float*)d_in[0];
    const float* xk = (const float*)d_in[1];
    const float* xv = (const float*)d_in[2];
    const float* WQ = (const float*)d_in[3];
    const float* bQ = (const float*)d_in[4];
    const float* WK = (const float*)d_in[5];
    const float* bK = (const float*)d_in[6];
    const float* WV = (const float*)d_in[7];
    const float* bV = (const float*)d_in[8];
    const float* WO = (const float*)d_in[9];
    const float* bO = (const float*)d_in[10];
    float* out = (float*)d_out;

    static int smem_set = 0;
    if (!smem_set) {
        cudaFuncSetAttribute(attn_mma_kernel,
                             cudaFuncAttributeMaxDynamicSharedMemorySize, 81920);
        smem_set = 1;
    }

    transpose_w_kernel<<<dim3(64, 64), dim3(32, 8)>>>(WQ, WK, WV, WO);
    proj_mma_kernel<<<dim3(16, 16, 3), 256>>>(xq, xk, xv, bQ, bK, bV);
    vtrans_kernel<<<dim3(64, 2, 16), dim3(32, 8)>>>();
    attn_mma_kernel<<<dim3(16, 16), 128, 81920>>>();
    outproj_mma_kernel<<<dim3(16, 8, 16), 256>>>(bO, out);
}

// round 7
// speedup vs baseline: 3.1354x; 1.3989x over previous
#include <cuda_runtime.h>
#include <cstdint>
#include <math.h>

#define SQ 2048
#define NH 16
#define DM 1024
#define DH 64

__device__ float g_q[NH * SQ * DH];
__device__ float g_k[NH * SQ * DH];
__device__ float g_v[NH * SQ * DH];
__device__ float g_vt[NH * DH * SQ];      // V^T: [h][e][s], tf32-rounded
__device__ float g_z[NH * SQ * DH];
__device__ float g_wt[3][NH * DH * DM];   // W^T, tf32-rounded
__device__ float g_wot[NH * DM * DH];     // W_O^T, tf32-rounded

__device__ __forceinline__ uint32_t smem_u32(const void* p) {
    uint32_t a;
    asm("{ .reg .u64 t; cvta.to.shared.u64 t, %1; cvt.u32.u64 %0, t; }" : "=r"(a) : "l"(p));
    return a;
}
#define SWZ128(x) ((x) ^ (((x) >> 3) & 0x70))

__device__ __forceinline__ float to_tf32(float x) {
    float y;
    asm("cvt.rna.tf32.f32 %0, %1;" : "=f"(y) : "f"(x));
    return y;
}
__device__ __forceinline__ void ldsm_x4(uint32_t& r0, uint32_t& r1, uint32_t& r2,
                                        uint32_t& r3, uint32_t addr) {
    asm volatile("ldmatrix.sync.aligned.m8n8.x4.shared.b16 {%0,%1,%2,%3}, [%4];"
                 : "=r"(r0), "=r"(r1), "=r"(r2), "=r"(r3) : "r"(addr));
}
__device__ __forceinline__ void mma_tf32(float* c, const uint32_t* a,
                                         uint32_t b0, uint32_t b1) {
    asm volatile(
        "mma.sync.aligned.m16n8k8.row.col.f32.tf32.tf32.f32 "
        "{%0,%1,%2,%3}, {%4,%5,%6,%7}, {%8,%9}, {%0,%1,%2,%3};"
        : "+f"(c[0]), "+f"(c[1]), "+f"(c[2]), "+f"(c[3])
        : "r"(a[0]), "r"(a[1]), "r"(a[2]), "r"(a[3]), "r"(b0), "r"(b1));
}
#define CP_ASYNC16(dst, src) \
    asm volatile("cp.async.cg.shared.global [%0], [%1], 16;" :: "r"(dst), "l"(src))
#define CP_COMMIT() asm volatile("cp.async.commit_group;" ::: "memory")
#define CP_WAIT(n)  asm volatile("cp.async.wait_group %0;" :: "n"(n) : "memory")

// ---------------- W transpose (+tf32 round) -----------------------------------
__global__ void transpose_w_kernel(const float* __restrict__ WQ, const float* __restrict__ WK,
                                   const float* __restrict__ WV, const float* __restrict__ WO)
{
    __shared__ float t[32][33];
    const int m = blockIdx.y >> 4, h = blockIdx.y & 15;
    const float* src; float* dst; int R, C;
    if (m == 0)      { src = WQ + (size_t)h*DM*DH; dst = g_wt[0] + (size_t)h*DH*DM; R = DM; C = DH; }
    else if (m == 1) { src = WK + (size_t)h*DM*DH; dst = g_wt[1] + (size_t)h*DH*DM; R = DM; C = DH; }
    else if (m == 2) { src = WV + (size_t)h*DM*DH; dst = g_wt[2] + (size_t)h*DH*DM; R = DM; C = DH; }
    else             { src = WO + (size_t)h*DH*DM; dst = g_wot   + (size_t)h*DM*DH; R = DH; C = DM; }
    const int nrt = R / 32, rt = blockIdx.x % nrt, ct = blockIdx.x / nrt;
    const int x = ct * 32 + threadIdx.x;
    #pragma unroll
    for (int j = 0; j < 4; j++)
        t[threadIdx.y + j*8][threadIdx.x] =
            to_tf32(src[(size_t)(rt*32 + threadIdx.y + j*8) * C + x]);
    __syncthreads();
    const int xo = rt * 32 + threadIdx.x;
    #pragma unroll
    for (int j = 0; j < 4; j++)
        dst[(size_t)(ct*32 + threadIdx.y + j*8) * R + xo] = t[threadIdx.x][threadIdx.y + j*8];
}

// ---------------- V transpose: g_v [h][s][e] -> g_vt [h][e][s] -----------------
__global__ void vtrans_kernel()
{
    __shared__ float t[32][33];
    const int h = blockIdx.z;
    const int s0 = blockIdx.x * 32, e0 = blockIdx.y * 32;
    #pragma unroll
    for (int j = 0; j < 4; j++)
        t[threadIdx.y + j*8][threadIdx.x] =
            g_v[((size_t)h*SQ + s0 + threadIdx.y + j*8) * DH + e0 + threadIdx.x];
    __syncthreads();
    #pragma unroll
    for (int j = 0; j < 4; j++)
        g_vt[((size_t)h*DH + e0 + threadIdx.y + j*8) * SQ + s0 + threadIdx.x] =
            t[threadIdx.x][threadIdx.y + j*8];
}

// ---------------- Projection via HMMA tf32, 3-stage cp.async -------------------
// dyn smem: A stages @ 0/16K/32K (48KB), B stages @ 49152 + i*8K (24KB) = 73728B
__global__ __launch_bounds__(256, 1) void proj_mma_kernel(
    const float* __restrict__ xq, const float* __restrict__ xk, const float* __restrict__ xv,
    const float* __restrict__ bQ, const float* __restrict__ bK, const float* __restrict__ bV)
{
    extern __shared__ uint8_t dsm[];
    const uint32_t sA = smem_u32(dsm);
    const uint32_t sB = sA + 49152;

    const int tid = threadIdx.x, w = tid >> 5, lane = tid & 31;
    const int h = blockIdx.y, which = blockIdx.z;
    const int s0 = blockIdx.x * 128;

    const float* X    = (which == 0) ? xq : (which == 1) ? xk : xv;
    const float* bias = (which == 0) ? bQ : (which == 1) ? bK : bV;
    const float* WT   = g_wt[which] + (size_t)h * DH * DM;
    float* out        = (which == 0) ? g_q : (which == 1) ? g_k : g_v;

    const int mw = w * 16;
    const int g  = lane >> 3, l7 = lane & 7;

    auto prefetch = [&](int c) {
        const int k0 = c * 32;
        const uint32_t ab = sA + (uint32_t)((c % 3) * 16384);
        const uint32_t bb = sB + (uint32_t)((c % 3) * 8192);
        #pragma unroll
        for (int i = 0; i < 4; i++) {
            int idx = tid + i * 256, r = idx >> 3, q = idx & 7;
            CP_ASYNC16(ab + SWZ128((uint32_t)(r*128 + q*16)),
                       &X[(((size_t)(s0 + r)) * NH + h) * DM + k0 + q*4]);
        }
        #pragma unroll
        for (int i = 0; i < 2; i++) {
            int idx = tid + i * 256, n = idx >> 3, q = idx & 7;
            CP_ASYNC16(bb + SWZ128((uint32_t)(n*128 + q*16)),
                       &WT[(size_t)n * DM + k0 + q*4]);
        }
    };

    float acc[8][4] = {};

    prefetch(0); CP_COMMIT();
    prefetch(1); CP_COMMIT();

    #pragma unroll 1
    for (int c = 0; c < 32; c++) {
        CP_WAIT(1);
        __syncthreads();
        if (c + 2 < 32) prefetch(c + 2);
        CP_COMMIT();

        const uint32_t sbA = sA + (uint32_t)((c % 3) * 16384);
        const uint32_t sbB = sB + (uint32_t)((c % 3) * 8192);
        #pragma unroll
        for (int kk = 0; kk < 4; kk++) {
            const int kb = kk * 32;
            uint32_t a[4];
            {
                int row = mw + ((g & 1) << 3) + l7;
                int byo = kb + ((g >> 1) << 4);
                ldsm_x4(a[0], a[1], a[2], a[3], sbA + SWZ128((uint32_t)(row*128 + byo)));
            }
            uint32_t b[16];
            #pragma unroll
            for (int nb = 0; nb < 4; nb++) {
                int row = nb * 16 + ((g >> 1) << 3) + l7;
                int byo = kb + ((g & 1) << 4);
                ldsm_x4(b[nb*4+0], b[nb*4+1], b[nb*4+2], b[nb*4+3],
                        sbB + SWZ128((uint32_t)(row*128 + byo)));
            }
            #pragma unroll
            for (int ni = 0; ni < 8; ni++)
                mma_tf32(acc[ni], a, b[(ni >> 1)*4 + (ni & 1)*2],
                                     b[(ni >> 1)*4 + (ni & 1)*2 + 1]);
        }
    }

    const int r0 = mw + (lane >> 2);
    const int ec = (lane & 3) * 2;

    #pragma unroll
    for (int ni = 0; ni < 8; ni++) {
        float bv0 = bias[h * DH + ni*8 + ec];
        float bv1 = bias[h * DH + ni*8 + ec + 1];
        acc[ni][0] += bv0; acc[ni][1] += bv1;
        acc[ni][2] += bv0; acc[ni][3] += bv1;
    }

    if (which < 2) {
        const float L2B = 0.41524101186092029f;
        #pragma unroll
        for (int ni = 0; ni < 4; ni++) {
            #pragma unroll
            for (int cc = 0; cc < 2; cc++) {
                int j = ni*8 + ec + cc;
                float invf = exp2f(-(float)j * L2B);
                #pragma unroll
                for (int rr = 0; rr < 2; rr++) {
                    float pos = (float)(s0 + r0 + rr*8);
                    float sn, cs; sincosf(pos * invf, &sn, &cs);
                    int ci = rr*2 + cc;
                    float x = acc[ni][ci], y = acc[ni+4][ci];
                    acc[ni][ci]   = x*cs - y*sn;
                    acc[ni+4][ci] = y*cs + x*sn;
                }
            }
        }
    }

    #pragma unroll
    for (int ni = 0; ni < 8; ni++) {
        int e = ni*8 + ec;
        *(float2*)&out[((size_t)h*SQ + s0 + r0    ) * DH + e] =
            make_float2(to_tf32(acc[ni][0]), to_tf32(acc[ni][1]));
        *(float2*)&out[((size_t)h*SQ + s0 + r0 + 8) * DH + e] =
            make_float2(to_tf32(acc[ni][2]), to_tf32(acc[ni][3]));
    }
}

// ---------------- Attention via HMMA tf32, cp.async double-buffered ------------
// dynamic smem: Q/P @0 (16KB), K @16384 (2x16KB), V @49152 (2x16KB) = 80KB
__global__ __launch_bounds__(128, 2) void attn_mma_kernel()
{
    extern __shared__ uint8_t dsm[];
    const uint32_t sQ = smem_u32(dsm);
    const uint32_t sK = sQ + 16384;
    const uint32_t sV = sQ + 49152;

    const int tid = threadIdx.x, w = tid >> 5, lane = tid & 31;
    const int h = blockIdx.y;
    const int g = lane >> 3, l7 = lane & 7;
    const int mw = w * 16;
    const int r_loc = lane >> 2, ec = (lane & 3) * 2;

    for (int rep = 0; rep < 2; rep++) {
        const int qb = rep ? (31 - (int)blockIdx.x) : (int)blockIdx.x;
        const int q0 = qb * 64;

        __syncthreads();
        #pragma unroll
        for (int i = 0; i < 8; i++) {
            int idx = tid + i * 128, r = idx >> 4, q = idx & 15;
            uint32_t off = (uint32_t)((q>>3)*8192) + SWZ128((uint32_t)(r*128 + (q&7)*16));
            CP_ASYNC16(sQ + off, &g_q[((size_t)h*SQ + q0 + r) * DH + q*4]);
        }
        CP_COMMIT();
        #pragma unroll
        for (int i = 0; i < 8; i++) {
            int idx = tid + i * 128, r = idx >> 4, q = idx & 15;
            uint32_t off = (uint32_t)((q>>3)*8192) + SWZ128((uint32_t)(r*128 + (q&7)*16));
            CP_ASYNC16(sK + off, &g_k [((size_t)h*SQ + r) * DH + q*4]);
            CP_ASYNC16(sV + off, &g_vt[((size_t)h*DH + r) * SQ + q*4]);
        }
        CP_COMMIT();
        CP_WAIT(1);
        __syncthreads();

        uint32_t qa[8][4];
        #pragma unroll
        for (int ds = 0; ds < 8; ds++) {
            int row = mw + ((g & 1) << 3) + l7;
            int byo = (ds & 3) * 32 + ((g >> 1) << 4);
            ldsm_x4(qa[ds][0], qa[ds][1], qa[ds][2], qa[ds][3],
                    sQ + (uint32_t)((ds >> 2)*8192) + SWZ128((uint32_t)(row*128 + byo)));
        }

        float m0 = -1e30f, m1 = -1e30f, l0 = 0.f, l1 = 0.f;
        float oa[8][4] = {};

        for (int kt = 0; kt <= qb; kt++) {
            const uint32_t kb_off = (uint32_t)((kt & 1) * 16384);
            CP_WAIT(0);
            __syncthreads();
            if (kt < qb) {
                const int kk0 = (kt + 1) * 64;
                const uint32_t nb_off = (uint32_t)(((kt + 1) & 1) * 16384);
                #pragma unroll
                for (int i = 0; i < 8; i++) {
                    int idx = tid + i * 128, r = idx >> 4, q = idx & 15;
                    uint32_t off = nb_off + (uint32_t)((q>>3)*8192)
                                 + SWZ128((uint32_t)(r*128 + (q&7)*16));
                    CP_ASYNC16(sK + off, &g_k [((size_t)h*SQ + kk0 + r) * DH + q*4]);
                    CP_ASYNC16(sV + off, &g_vt[((size_t)h*DH + r) * SQ + kk0 + q*4]);
                }
                CP_COMMIT();
            }

            float sacc[8][4] = {};
            #pragma unroll
            for (int ds = 0; ds < 8; ds++) {
                uint32_t b[16];
                #pragma unroll
                for (int nb = 0; nb < 4; nb++) {
                    int row = nb*16 + ((g >> 1) << 3) + l7;
                    int byo = (ds & 3)*32 + ((g & 1) << 4);
                    ldsm_x4(b[nb*4+0], b[nb*4+1], b[nb*4+2], b[nb*4+3],
                            sK + kb_off + (uint32_t)((ds >> 2)*8192)
                               + SWZ128((uint32_t)(row*128 + byo)));
                }
                #pragma unroll
                for (int ni = 0; ni < 8; ni++)
                    mma_tf32(sacc[ni], qa[ds], b[(ni>>1)*4 + (ni&1)*2],
                                               b[(ni>>1)*4 + (ni&1)*2 + 1]);
            }

            const bool diag = (kt == qb);
            #pragma unroll
            for (int ni = 0; ni < 8; ni++) {
                #pragma unroll
                for (int ci = 0; ci < 4; ci++) sacc[ni][ci] *= 0.125f;
                if (diag) {
                    int col = ni*8 + ec;
                    int row0 = mw + r_loc, row1 = row0 + 8;
                    if (col     > row0) sacc[ni][0] = -1e30f;
                    if (col + 1 > row0) sacc[ni][1] = -1e30f;
                    if (col     > row1) sacc[ni][2] = -1e30f;
                    if (col + 1 > row1) sacc[ni][3] = -1e30f;
                }
            }

            float rx0 = -1e30f, rx1 = -1e30f;
            #pragma unroll
            for (int ni = 0; ni < 8; ni++) {
                rx0 = fmaxf(rx0, fmaxf(sacc[ni][0], sacc[ni][1]));
                rx1 = fmaxf(rx1, fmaxf(sacc[ni][2], sacc[ni][3]));
            }
            rx0 = fmaxf(rx0, __shfl_xor_sync(0xffffffffu, rx0, 1));
            rx0 = fmaxf(rx0, __shfl_xor_sync(0xffffffffu, rx0, 2));
            rx1 = fmaxf(rx1, __shfl_xor_sync(0xffffffffu, rx1, 1));
            rx1 = fmaxf(rx1, __shfl_xor_sync(0xffffffffu, rx1, 2));
            float mn0 = fmaxf(m0, rx0), mn1 = fmaxf(m1, rx1);
            float c0 = __expf(m0 - mn0), c1 = __expf(m1 - mn1);
            float su0 = 0.f, su1 = 0.f;
            #pragma unroll
            for (int ni = 0; ni < 8; ni++) {
                sacc[ni][0] = __expf(sacc[ni][0] - mn0);
                sacc[ni][1] = __expf(sacc[ni][1] - mn0);
                sacc[ni][2] = __expf(sacc[ni][2] - mn1);
                sacc[ni][3] = __expf(sacc[ni][3] - mn1);
                su0 += sacc[ni][0] + sacc[ni][1];
                su1 += sacc[ni][2] + sacc[ni][3];
            }
            su0 += __shfl_xor_sync(0xffffffffu, su0, 1);
            su0 += __shfl_xor_sync(0xffffffffu, su0, 2);
            su1 += __shfl_xor_sync(0xffffffffu, su1, 1);
            su1 += __shfl_xor_sync(0xffffffffu, su1, 2);
            l0 = l0 * c0 + su0; l1 = l1 * c1 + su1;
            m0 = mn0; m1 = mn1;
            #pragma unroll
            for (int ni = 0; ni < 8; ni++) {
                oa[ni][0] *= c0; oa[ni][1] *= c0;
                oa[ni][2] *= c1; oa[ni][3] *= c1;
            }

            #pragma unroll
            for (int ni = 0; ni < 8; ni++) {
                int col = ni*8 + ec, ch = col >> 5, cc = col & 31;
                int row0 = mw + r_loc;
                float2 p0 = make_float2(to_tf32(sacc[ni][0]), to_tf32(sacc[ni][1]));
                float2 p1 = make_float2(to_tf32(sacc[ni][2]), to_tf32(sacc[ni][3]));
                *(float2*)(dsm + ch*8192 + SWZ128((uint32_t)(row0*128 + cc*4))) = p0;
                *(float2*)(dsm + ch*8192 + SWZ128((uint32_t)((row0+8)*128 + cc*4))) = p1;
            }
            __syncwarp();

            #pragma unroll
            for (int ks = 0; ks < 8; ks++) {
                uint32_t a[4];
                int row = mw + ((g & 1) << 3) + l7;
                int byo = (ks & 3)*32 + ((g >> 1) << 4);
                ldsm_x4(a[0], a[1], a[2], a[3],
                        sQ + (uint32_t)((ks >> 2)*8192) + SWZ128((uint32_t)(row*128 + byo)));
                uint32_t b[16];
                #pragma unroll
                for (int nb = 0; nb < 4; nb++) {
                    int rowb = nb*16 + ((g >> 1) << 3) + l7;
                    int byob = (ks & 3)*32 + ((g & 1) << 4);
                    ldsm_x4(b[nb*4+0], b[nb*4+1], b[nb*4+2], b[nb*4+3],
                            sV + kb_off + (uint32_t)((ks >> 2)*8192)
                               + SWZ128((uint32_t)(rowb*128 + byob)));
                }
                #pragma unroll
                for (int ni = 0; ni < 8; ni++)
                    mma_tf32(oa[ni], a, b[(ni>>1)*4 + (ni&1)*2],
                                        b[(ni>>1)*4 + (ni&1)*2 + 1]);
            }
        }

        float inv0 = 1.f / l0, inv1 = 1.f / l1;
        int row0 = q0 + mw + r_loc;
        #pragma unroll
        for (int ni = 0; ni < 8; ni++) {
            int e = ni*8 + ec;
            *(float2*)&g_z[((size_t)h*SQ + row0    ) * DH + e] =
                make_float2(to_tf32(oa[ni][0]*inv0), to_tf32(oa[ni][1]*inv0));
            *(float2*)&g_z[((size_t)h*SQ + row0 + 8) * DH + e] =
                make_float2(to_tf32(oa[ni][2]*inv1), to_tf32(oa[ni][3]*inv1));
        }
    }
}

// ---------------- Output projection via HMMA tf32, cp.async --------------------
// dyn smem: A (Z 128x64) @0 2 chunks of 16KB; B (WOT 128x64) @32768, = 65536B
__global__ __launch_bounds__(256, 1) void outproj_mma_kernel(
    const float* __restrict__ bO, float* __restrict__ out)
{
    extern __shared__ uint8_t dsm[];
    const uint32_t sA = smem_u32(dsm);
    const uint32_t sB = sA + 32768;

    const int tid = threadIdx.x, w = tid >> 5, lane = tid & 31;
    const int s0 = blockIdx.x * 128, d0 = blockIdx.y * 128, h = blockIdx.z;
    const float* WOT = g_wot + (size_t)h * DM * DH;

    const int mw = w * 16;
    const int g  = lane >> 3, l7 = lane & 7;

    #pragma unroll
    for (int i = 0; i < 8; i++) {
        int idx = tid + i * 256, r = idx >> 4, q = idx & 15;
        uint32_t off = (uint32_t)((q>>3)*16384) + SWZ128((uint32_t)(r*128 + (q&7)*16));
        CP_ASYNC16(sA + off, &g_z[((size_t)h*SQ + s0 + r) * DH + q*4]);
        CP_ASYNC16(sB + off, &WOT[(size_t)(d0 + r) * DH + q*4]);
    }
    CP_COMMIT();
    CP_WAIT(0);
    __syncthreads();

    float acc[16][4] = {};

    #pragma unroll
    for (int ks = 0; ks < 8; ks++) {
        uint32_t a[4];
        {
            int row = mw + ((g & 1) << 3) + l7;
            int byo = (ks & 3)*32 + ((g >> 1) << 4);
            ldsm_x4(a[0], a[1], a[2], a[3],
                    sA + (uint32_t)((ks >> 2)*16384) + SWZ128((uint32_t)(row*128 + byo)));
        }
        uint32_t b[32];
        #pragma unroll
        for (int nb = 0; nb < 8; nb++) {
            int row = nb * 16 + ((g >> 1) << 3) + l7;
            int byo = (ks & 3)*32 + ((g & 1) << 4);
            ldsm_x4(b[nb*4+0], b[nb*4+1], b[nb*4+2], b[nb*4+3],
                    sB + (uint32_t)((ks >> 2)*16384) + SWZ128((uint32_t)(row*128 + byo)));
        }
        #pragma unroll
        for (int ni = 0; ni < 16; ni++)
            mma_tf32(acc[ni], a, b[(ni >> 1)*4 + (ni & 1)*2],
                                 b[(ni >> 1)*4 + (ni & 1)*2 + 1]);
    }

    const int r0 = mw + (lane >> 2);
    const int ec = (lane & 3) * 2;
    #pragma unroll
    for (int ni = 0; ni < 16; ni++) {
        int dg = d0 + ni*8 + ec;
        float b0 = bO[dg] * 0.0625f, b1 = bO[dg + 1] * 0.0625f;
        int sg0 = s0 + r0, sg1 = sg0 + 8;
        *(float2*)&out[((size_t)sg0 * NH + h) * DM + dg] = make_float2(acc[ni][0] + b0, acc[ni][1] + b1);
        *(float2*)&out[((size_t)sg1 * NH + h) * DM + dg] = make_float2(acc[ni][2] + b0, acc[ni][3] + b1);
    }
}

// -------------------------------------------------------------------------------
extern "C" void kernel_launch(void* const* d_in, const int* in_sizes, int n_in,
                              void* d_out, int out_size)
{
    (void)in_sizes; (void)n_in; (void)out_size;
    const float* xq = (const float*)d_in[0];
    const float* xk = (const float*)d_in[1];
    const float* xv = (const float*)d_in[2];
    const float* WQ = (const float*)d_in[3];
    const float* bQ = (const float*)d_in[4];
    const float* WK = (const float*)d_in[5];
    const float* bK = (const float*)d_in[6];
    const float* WV = (const float*)d_in[7];
    const float* bV = (const float*)d_in[8];
    const float* WO = (const float*)d_in[9];
    const float* bO = (const float*)d_in[10];
    float* out = (float*)d_out;

    static int smem_set = 0;
    if (!smem_set) {
        cudaFuncSetAttribute(attn_mma_kernel,
                             cudaFuncAttributeMaxDynamicSharedMemorySize, 81920);
        cudaFuncSetAttribute(proj_mma_kernel,
                             cudaFuncAttributeMaxDynamicSharedMemorySize, 73728);
        cudaFuncSetAttribute(outproj_mma_kernel,
                             cudaFuncAttributeMaxDynamicSharedMemorySize, 65536);
        smem_set = 1;
    }

    transpose_w_kernel<<<dim3(64, 64), dim3(32, 8)>>>(WQ, WK, WV, WO);
    proj_mma_kernel<<<dim3(16, 16, 3), 256, 73728>>>(xq, xk, xv, bQ, bK, bV);
    vtrans_kernel<<<dim3(64, 2, 16), dim3(32, 8)>>>();
    attn_mma_kernel<<<dim3(16, 16), 128, 81920>>>();
    outproj_mma_kernel<<<dim3(16, 8, 16), 256, 65536>>>(bO, out);
}